// round 10
// baseline (speedup 1.0000x reference)
#include <cuda_runtime.h>
#include <cuda_fp16.h>
#include <math.h>
#include <cstdint>

#define BB    8
#define NN    4096
#define CC    512
#define NTOK  (BB*NN)        // 32768 tokens
#define HEADS 8
#define HD    64
#define HH    64
#define WW    64
#define EPSF  1e-5f
#define CLAMPF 100.0f

// ---------------- scratch (static device globals; no runtime alloc) ----------
__device__ __half g_normedh[NTOK*CC];              // 32 MB (GEMM1 A)
__device__ __half g_qkvh[(size_t)NTOK*3*CC];       // 96 MB (GEMM1 out, fp16)
__device__ __half g_attnh[NTOK*CC];                // 32 MB (GEMM2 A)
__device__ float g_attnproj[NTOK*CC];              // 64 MB
__device__ float g_y[NTOK*CC];                     // 64 MB
__device__ float g_mu[NTOK];                       // LN2 per-token mean
__device__ float g_rinv[NTOK];                     // LN2 per-token 1/std
__device__ float g_kv[BB*HEADS*HD*HD];
__device__ float g_ksum[BB*HEADS*HD];
__device__ float g_sum[CC];
__device__ float g_sumsq[CC];
__device__ __half g_wqkvTh[3*CC*CC];               // [1536,512] fp16 transposed
__device__ __half g_woutTh[CC*CC];                 // [512,512]  fp16 transposed

// ============================ PTX helpers ====================================
__device__ __forceinline__ uint32_t smem_u32(const void* p){
    uint32_t a;
    asm("{ .reg .u64 t; cvta.to.shared.u64 t, %1; cvt.u32.u64 %0, t; }"
        : "=r"(a) : "l"(p));
    return a;
}
__device__ __forceinline__ void cpa16(uint32_t dst, const void* src){
    asm volatile("cp.async.ca.shared.global [%0], [%1], 16;"
                 :: "r"(dst), "l"(src) : "memory");
}
__device__ __forceinline__ void cpa_commit(){
    asm volatile("cp.async.commit_group;" ::: "memory");
}
template<int N> __device__ __forceinline__ void cpa_wait(){
    asm volatile("cp.async.wait_group %0;" :: "n"(N) : "memory");
}
__device__ __forceinline__ void mma_f16(float* d, const uint32_t* a, const uint32_t* b){
    asm volatile("mma.sync.aligned.m16n8k16.row.col.f32.f16.f16.f32 "
        "{%0,%1,%2,%3}, {%4,%5,%6,%7}, {%8,%9}, {%0,%1,%2,%3};"
        : "+f"(d[0]), "+f"(d[1]), "+f"(d[2]), "+f"(d[3])
        : "r"(a[0]), "r"(a[1]), "r"(a[2]), "r"(a[3]), "r"(b[0]), "r"(b[1]));
}
__device__ __forceinline__ void ldsm4(uint32_t& r0, uint32_t& r1,
                                      uint32_t& r2, uint32_t& r3, uint32_t addr){
    asm volatile("ldmatrix.sync.aligned.m8n8.x4.shared.b16 {%0,%1,%2,%3}, [%4];"
        : "=r"(r0), "=r"(r1), "=r"(r2), "=r"(r3) : "r"(addr));
}

// ============================ mma.sync fp16 GEMM =============================
// D[M,Nn] = A[M,512] @ Bt[Nn,512]^T + bias, relu on cols < nrelu.
// CTA 128x128, 8 warps (4m x 2n), warp tile 32x64. BK=32, ldmatrix fragments.
#define GK    512
#define GBK   32
#define KPADH 40              // halves per row (80B stride; conflict-free LDSM)
#define NKT   (GK/GBK)        // 16 k-tiles

template<typename OUT>
__global__ void __launch_bounds__(256)
gemm_mma_kernel(const __half* __restrict__ A,
                const __half* __restrict__ Bt,
                const float* __restrict__ bias, OUT* __restrict__ Cout,
                int Nn, int nrelu)
{
    __shared__ __half As[2][128][KPADH];
    __shared__ __half Bs[2][128][KPADH];
    int tid = threadIdx.x;
    int wid = tid >> 5, lane = tid & 31;
    int gid = lane >> 2, tig = lane & 3;
    int warpM = (wid >> 1) * 32;
    int warpN = (wid & 1) * 64;
    int row0 = blockIdx.y * 128, col0 = blockIdx.x * 128;
    const __half* Ab = A  + (size_t)row0 * GK;
    const __half* Bb = Bt + (size_t)col0 * GK;

    int q0 = tid, q1 = tid + 256;
    int r0 = q0 >> 2, c0 = q0 & 3;
    int r1 = q1 >> 2, c1 = q1 & 3;
    uint32_t sA0 = smem_u32(&As[0][r0][0]) + c0 * 16;
    uint32_t sA1 = smem_u32(&As[0][r1][0]) + c1 * 16;
    uint32_t sB0 = smem_u32(&Bs[0][r0][0]) + c0 * 16;
    uint32_t sB1 = smem_u32(&Bs[0][r1][0]) + c1 * 16;
    const uint32_t stageOff = 128 * KPADH * 2;

    // ldmatrix base addresses (per-lane)
    int aRow = warpM + (lane & 15);           // + mi*16
    int aCol = (lane >> 4) * 8;               // + k0
    int bRow = warpN + (lane >> 4) * 8 + (lane & 7);   // + p*16
    int bCol = ((lane >> 3) & 1) * 8;         // + k0
    uint32_t aBase = smem_u32(&As[0][aRow][aCol]);
    uint32_t bBase = smem_u32(&Bs[0][bRow][bCol]);

    float acc[2][8][4];
    #pragma unroll
    for (int mi = 0; mi < 2; mi++)
        #pragma unroll
        for (int ni = 0; ni < 8; ni++)
            #pragma unroll
            for (int r = 0; r < 4; r++) acc[mi][ni][r] = 0.f;

    auto load_tile = [&](int t, int b){
        int k0 = t * GBK;
        uint32_t so = b * stageOff;
        cpa16(sA0 + so, Ab + (size_t)r0 * GK + k0 + c0 * 8);
        cpa16(sA1 + so, Ab + (size_t)r1 * GK + k0 + c1 * 8);
        cpa16(sB0 + so, Bb + (size_t)r0 * GK + k0 + c0 * 8);
        cpa16(sB1 + so, Bb + (size_t)r1 * GK + k0 + c1 * 8);
    };

    load_tile(0, 0);
    cpa_commit();

    for (int t = 0; t < NKT; t++){
        int cb = t & 1;
        if (t + 1 < NKT) load_tile(t + 1, (t + 1) & 1);
        cpa_commit();
        cpa_wait<1>();
        __syncthreads();
        uint32_t stage = cb * stageOff;
        #pragma unroll
        for (int ks = 0; ks < 2; ks++){
            int k0 = ks * 16;
            uint32_t a[2][4], bfr[8][2];
            #pragma unroll
            for (int mi = 0; mi < 2; mi++){
                uint32_t ad = aBase + stage + (mi * 16 * KPADH + k0) * 2;
                ldsm4(a[mi][0], a[mi][1], a[mi][2], a[mi][3], ad);
            }
            #pragma unroll
            for (int p = 0; p < 4; p++){
                uint32_t bd = bBase + stage + (p * 16 * KPADH + k0) * 2;
                ldsm4(bfr[2*p][0], bfr[2*p][1], bfr[2*p+1][0], bfr[2*p+1][1], bd);
            }
            #pragma unroll
            for (int mi = 0; mi < 2; mi++)
                #pragma unroll
                for (int ni = 0; ni < 8; ni++)
                    mma_f16(acc[mi][ni], a[mi], bfr[ni]);
        }
        __syncthreads();
    }

    // epilogue: bias + optional relu
    #pragma unroll
    for (int mi = 0; mi < 2; mi++){
        #pragma unroll
        for (int rr = 0; rr < 2; rr++){
            int r = row0 + warpM + mi * 16 + rr * 8 + gid;
            #pragma unroll
            for (int ni = 0; ni < 8; ni++){
                int c = col0 + warpN + ni * 8 + tig * 2;
                float ox = acc[mi][ni][rr * 2 + 0] + bias[c + 0];
                float oy = acc[mi][ni][rr * 2 + 1] + bias[c + 1];
                if (c < nrelu){
                    ox = fmaxf(ox, 0.f);
                    oy = fmaxf(oy, 0.f);
                }
                if constexpr (sizeof(OUT) == 4) {
                    float2 o{ox, oy};
                    *(float2*)((float*)Cout + (size_t)r * Nn + c) = o;
                } else {
                    __half2 o{__float2half(ox), __float2half(oy)};
                    *(__half2*)((__half*)Cout + (size_t)r * Nn + c) = o;
                }
            }
        }
    }
}

// ---------------- merged weight transpose -> fp16 ----------------------------
// blockIdx.x in [0,48): qkv_w [512,1536]; [48,64): out_w [512,512]
__global__ void transpose_kernel(const float* __restrict__ qkvw,
                                 const float* __restrict__ outw,
                                 __half* __restrict__ qkvT,
                                 __half* __restrict__ outT)
{
    __shared__ float tile[32][33];
    const float* in; __half* outp; int Cc, bxi;
    if (blockIdx.x < 48){ in = qkvw; outp = qkvT; Cc = 1536; bxi = blockIdx.x; }
    else                { in = outw; outp = outT; Cc = 512;  bxi = blockIdx.x - 48; }
    int bx = bxi * 32, by = blockIdx.y * 32;
    int tx = threadIdx.x, ty = threadIdx.y;   // 32 x 8
    #pragma unroll
    for (int i = 0; i < 32; i += 8)
        tile[ty + i][tx] = in[(size_t)(by + ty + i) * Cc + bx + tx];
    __syncthreads();
    #pragma unroll
    for (int i = 0; i < 32; i += 8)
        outp[(size_t)(bx + ty + i) * 512 + by + tx] = __float2half(tile[tx][ty + i]);
}

// ---------------- layernorm over C=512 -> fp16 -------------------------------
__global__ void ln_kernel(const float* __restrict__ in,
                          const float* __restrict__ gamma,
                          const float* __restrict__ beta,
                          __half* __restrict__ out)
{
    int token = blockIdx.x;
    const float4* row = (const float4*)(in + (size_t)token * CC);
    int tid = threadIdx.x;
    float4 v = row[tid];
    float s  = v.x + v.y + v.z + v.w;
    float sq = v.x*v.x + v.y*v.y + v.z*v.z + v.w*v.w;
    #pragma unroll
    for (int o = 16; o; o >>= 1) {
        s  += __shfl_xor_sync(0xffffffffu, s,  o);
        sq += __shfl_xor_sync(0xffffffffu, sq, o);
    }
    __shared__ float ss[4], ssq[4];
    if ((tid & 31) == 0) { ss[tid >> 5] = s; ssq[tid >> 5] = sq; }
    __syncthreads();
    float ts = ss[0] + ss[1] + ss[2] + ss[3];
    float tq = ssq[0] + ssq[1] + ssq[2] + ssq[3];
    float mean = ts * (1.0f / CC);
    float var  = tq * (1.0f / CC) - mean * mean;
    float inv  = rsqrtf(var + EPSF);
    float4 g4 = ((const float4*)gamma)[tid];
    float4 b4 = ((const float4*)beta)[tid];
    __half2 p0{__float2half((v.x - mean) * inv * g4.x + b4.x),
               __float2half((v.y - mean) * inv * g4.y + b4.y)};
    __half2 p1{__float2half((v.z - mean) * inv * g4.z + b4.z),
               __float2half((v.w - mean) * inv * g4.w + b4.w)};
    uint2 pk;
    pk.x = *(uint32_t*)&p0;
    pk.y = *(uint32_t*)&p1;
    ((uint2*)(out + (size_t)token * CC))[tid] = pk;
}

// ---------------- LN2 stats: per-token mean + 1/std --------------------------
__global__ void ln_stats_kernel(const float* __restrict__ in,
                                float* __restrict__ mu, float* __restrict__ rinv)
{
    int token = blockIdx.x;
    const float4* row = (const float4*)(in + (size_t)token * CC);
    int tid = threadIdx.x;
    float4 v = row[tid];
    float s  = v.x + v.y + v.z + v.w;
    float sq = v.x*v.x + v.y*v.y + v.z*v.z + v.w*v.w;
    #pragma unroll
    for (int o = 16; o; o >>= 1) {
        s  += __shfl_xor_sync(0xffffffffu, s,  o);
        sq += __shfl_xor_sync(0xffffffffu, sq, o);
    }
    __shared__ float ss[4], ssq[4];
    if ((tid & 31) == 0) { ss[tid >> 5] = s; ssq[tid >> 5] = sq; }
    __syncthreads();
    if (tid == 0){
        float ts = ss[0] + ss[1] + ss[2] + ss[3];
        float tq = ssq[0] + ssq[1] + ssq[2] + ssq[3];
        float mean = ts * (1.0f / CC);
        float var  = tq * (1.0f / CC) - mean * mean;
        mu[token]   = mean;
        rinv[token] = rsqrtf(var + EPSF);
    }
}

// ---------------- zero scratch accumulators ---------------------------------
__global__ void zero_kernel()
{
    int i = blockIdx.x * blockDim.x + threadIdx.x;
    if (i < BB*HEADS*HD*HD) g_kv[i] = 0.f;
    if (i < BB*HEADS*HD)    g_ksum[i] = 0.f;
    if (i < CC)           { g_sum[i] = 0.f; g_sumsq[i] = 0.f; }
}

// ---------------- kv = k^T v per (b,h); ksum = sum_n k (fp16 in) -------------
__global__ __launch_bounds__(256)
void kv_kernel(const __half* __restrict__ qkv)
{
    int bh = blockIdx.x;
    int b = bh >> 3, h = bh & 7;
    const __half* kbase = qkv + (size_t)(b*NN)*1536 +  512 + h*64;
    const __half* vbase = qkv + (size_t)(b*NN)*1536 + 1024 + h*64;
    __shared__ float ks[64][64];
    __shared__ float vs[64][64];
    int tid = threadIdx.x;
    int lr  = tid >> 3;
    int lc8 = (tid & 7) * 8;
    int ty = tid >> 4, tx = tid & 15;
    float acc[4][4];
    #pragma unroll
    for (int i = 0; i < 4; i++)
        #pragma unroll
        for (int j = 0; j < 4; j++) acc[i][j] = 0.f;
    float ksum8[8];
    #pragma unroll
    for (int j = 0; j < 8; j++) ksum8[j] = 0.f;
    int n0 = blockIdx.y * 256;
    for (int s = 0; s < 4; s++) {
        int base = n0 + s * 64;
        #pragma unroll
        for (int p = 0; p < 2; p++) {
            int r = p * 32 + lr;
            uint4 kk = *(const uint4*)(kbase + (size_t)(base + r) * 1536 + lc8);
            uint4 vv = *(const uint4*)(vbase + (size_t)(base + r) * 1536 + lc8);
            const __half2* kh = (const __half2*)&kk;
            const __half2* vh = (const __half2*)&vv;
            #pragma unroll
            for (int j = 0; j < 4; j++){
                float2 kf = __half22float2(kh[j]);
                float2 vf = __half22float2(vh[j]);
                ks[r][lc8 + 2*j    ] = kf.x;
                ks[r][lc8 + 2*j + 1] = kf.y;
                vs[r][lc8 + 2*j    ] = vf.x;
                vs[r][lc8 + 2*j + 1] = vf.y;
                ksum8[2*j]     += kf.x;
                ksum8[2*j + 1] += kf.y;
            }
        }
        __syncthreads();
        #pragma unroll 8
        for (int n = 0; n < 64; n++) {
            float rk[4], rv[4];
            *(float4*)rk = *(const float4*)&ks[n][ty * 4];
            *(float4*)rv = *(const float4*)&vs[n][tx * 4];
            #pragma unroll
            for (int i = 0; i < 4; i++)
                #pragma unroll
                for (int j = 0; j < 4; j++)
                    acc[i][j] += rk[i] * rv[j];
        }
        __syncthreads();
    }
    float* kvout = g_kv + bh * 4096;
    #pragma unroll
    for (int i = 0; i < 4; i++)
        #pragma unroll
        for (int j = 0; j < 4; j++)
            atomicAdd(&kvout[(ty*4 + i) * 64 + tx*4 + j], acc[i][j]);
    #pragma unroll
    for (int j = 0; j < 8; j++){
        ksum8[j] += __shfl_xor_sync(0xffffffffu, ksum8[j], 8);
        ksum8[j] += __shfl_xor_sync(0xffffffffu, ksum8[j], 16);
    }
    if ((tid & 31) < 8){
        #pragma unroll
        for (int j = 0; j < 8; j++)
            atomicAdd(&g_ksum[bh * 64 + lc8 + j], ksum8[j]);
    }
}

// ---------------- attn = (q @ kv) / max(q . norm, 100) -> fp16 ---------------
__global__ __launch_bounds__(256)
void attn_kernel(const __half* __restrict__ qkv, __half* __restrict__ attn)
{
    int bh = blockIdx.x;
    int b = bh >> 3, h = bh & 7;
    __shared__ float kvs[64][64];
    __shared__ float norms[64];
    __shared__ float qs[4][64];
    int tid = threadIdx.x;
    for (int i = tid; i < 4096; i += 256)
        kvs[i >> 6][i & 63] = g_kv[bh * 4096 + i];
    if (tid < 64) norms[tid] = fmaxf(g_ksum[bh * 64 + tid], CLAMPF);
    __syncthreads();
    int tg = tid >> 6;
    int e  = tid & 63;
    const __half* qbase = qkv + (size_t)(b*NN)*1536 + h*64;
    for (int it = 0; it < 8; it++) {
        int n = blockIdx.y * 32 + it * 4 + tg;
        qs[tg][e] = __half2float(qbase[(size_t)n * 1536 + e]);
        __syncthreads();
        float acc = 0.f, den = 0.f;
        #pragma unroll
        for (int d = 0; d < 64; d++) {
            float qd = qs[tg][d];
            acc += qd * kvs[d][e];
            den += qd * norms[d];
        }
        den = fmaxf(den, CLAMPF);
        attn[(size_t)(b*NN + n) * CC + h*64 + e] = __float2half(acc / den);
        __syncthreads();
    }
}

// ---------------- conv1: fused LN2-apply + dw7x7 + gelu + bn stats -----------
__global__ __launch_bounds__(256)
void conv1_kernel(const float* __restrict__ ap, const float* __restrict__ cw,
                  const float* __restrict__ cb, const float* __restrict__ lg,
                  const float* __restrict__ lb)
{
    int b  = blockIdx.z;
    int c0 = blockIdx.y * 32;
    int h0 = (blockIdx.x >> 3) * 8;
    int w0 = (blockIdx.x & 7) * 8;
    __shared__ float ins[14][14][32];
    __shared__ float ws[32][49];
    __shared__ float sg[32], sb[32];
    __shared__ float rsum[8][32], rsq[8][32];
    int tid = threadIdx.x;
    if (tid < 32){ sg[tid] = lg[c0 + tid]; sb[tid] = lb[c0 + tid]; }
    for (int i = tid; i < 32 * 49; i += 256)
        ws[i / 49][i % 49] = cw[(c0 + i / 49) * 49 + (i % 49)];
    __syncthreads();
    for (int i = tid; i < 14 * 14 * 32; i += 256) {
        int ic = i & 31; int pos = i >> 5;
        int iw = pos % 14, ih = pos / 14;
        int gh = h0 + ih - 3, gw = w0 + iw - 3;
        float v = 0.f;
        if (gh >= 0 && gh < HH && gw >= 0 && gw < WW){
            size_t tok = (size_t)(b*NN) + gh*WW + gw;
            float a = ap[tok * CC + c0 + ic];
            v = (a - g_mu[tok]) * g_rinv[tok] * sg[ic] + sb[ic];
        }
        ins[ih][iw][ic] = v;
    }
    __syncthreads();
    int oc = tid & 31;
    int ow = tid >> 5;
    float wr[49];
    #pragma unroll
    for (int j = 0; j < 49; j++) wr[j] = ws[oc][j];
    float bias = cb[c0 + oc];
    float acc[8];
    #pragma unroll
    for (int oh = 0; oh < 8; oh++) acc[oh] = bias;
    #pragma unroll
    for (int ih = 0; ih < 14; ih++){
        float v[7];
        #pragma unroll
        for (int dw = 0; dw < 7; dw++) v[dw] = ins[ih][ow + dw][oc];
        #pragma unroll
        for (int oh = 0; oh < 8; oh++){
            int dh = ih - oh;
            if (dh >= 0 && dh < 7){
                #pragma unroll
                for (int dw = 0; dw < 7; dw++)
                    acc[oh] += v[dw] * wr[dh * 7 + dw];
            }
        }
    }
    float psum = 0.f, psq = 0.f;
    #pragma unroll
    for (int oh = 0; oh < 8; oh++){
        float yv = acc[oh] * normcdff(acc[oh]);
        g_y[((size_t)(b*NN) + (h0+oh)*WW + (w0+ow)) * CC + c0 + oc] = yv;
        psum += yv; psq += yv * yv;
    }
    rsum[ow][oc] = psum; rsq[ow][oc] = psq;
    __syncthreads();
    if (tid < 32) {
        float s = 0.f, q = 0.f;
        #pragma unroll
        for (int i = 0; i < 8; i++) { s += rsum[i][tid]; q += rsq[i][tid]; }
        atomicAdd(&g_sum[c0 + tid], s);
        atomicAdd(&g_sumsq[c0 + tid], q);
    }
}

// ---------------- conv2: BN-apply + depthwise 7x7 + triple residual ----------
__global__ __launch_bounds__(256)
void conv2_kernel(const float* __restrict__ x, const float* __restrict__ cw,
                  const float* __restrict__ cb, const float* __restrict__ bng,
                  const float* __restrict__ bnb, float* __restrict__ out)
{
    int b  = blockIdx.z;
    int c0 = blockIdx.y * 32;
    int h0 = (blockIdx.x >> 3) * 8;
    int w0 = (blockIdx.x & 7) * 8;
    __shared__ float ins[14][14][32];
    __shared__ float ws[32][49];
    __shared__ float scs[32], shs[32];
    int tid = threadIdx.x;
    if (tid < 32) {
        int c = c0 + tid;
        float m   = g_sum[c]   * (1.0f / (float)NTOK);
        float var = g_sumsq[c] * (1.0f / (float)NTOK) - m * m;
        float inv = rsqrtf(var + EPSF);
        float sc = bng[c] * inv;
        scs[tid] = sc;
        shs[tid] = bnb[c] - m * sc;
    }
    for (int i = tid; i < 32 * 49; i += 256)
        ws[i / 49][i % 49] = cw[(c0 + i / 49) * 49 + (i % 49)];
    __syncthreads();
    for (int i = tid; i < 14 * 14 * 32; i += 256) {
        int ic = i & 31; int pos = i >> 5;
        int iw = pos % 14, ih = pos / 14;
        int gh = h0 + ih - 3, gw = w0 + iw - 3;
        float v = 0.f;
        if (gh >= 0 && gh < HH && gw >= 0 && gw < WW)
            v = g_y[((size_t)(b*NN) + gh*WW + gw) * CC + c0 + ic] * scs[ic] + shs[ic];
        ins[ih][iw][ic] = v;
    }
    __syncthreads();
    int oc = tid & 31;
    int ow = tid >> 5;
    float wr[49];
    #pragma unroll
    for (int j = 0; j < 49; j++) wr[j] = ws[oc][j];
    float bias = cb[c0 + oc];
    float acc[8];
    #pragma unroll
    for (int oh = 0; oh < 8; oh++) acc[oh] = bias;
    #pragma unroll
    for (int ih = 0; ih < 14; ih++){
        float v[7];
        #pragma unroll
        for (int dw = 0; dw < 7; dw++) v[dw] = ins[ih][ow + dw][oc];
        #pragma unroll
        for (int oh = 0; oh < 8; oh++){
            int dh = ih - oh;
            if (dh >= 0 && dh < 7){
                #pragma unroll
                for (int dw = 0; dw < 7; dw++)
                    acc[oh] += v[dw] * wr[dh * 7 + dw];
            }
        }
    }
    #pragma unroll
    for (int oh = 0; oh < 8; oh++){
        size_t idx = ((size_t)(b*NN) + (h0+oh)*WW + (w0+ow)) * CC + c0 + oc;
        out[idx] = x[idx] + g_attnproj[idx] + acc[oh];
    }
}

// ---------------- launch ----------------------------------------------------
extern "C" void kernel_launch(void* const* d_in, const int* in_sizes, int n_in,
                              void* d_out, int out_size)
{
    const float* x      = (const float*)d_in[0];
    const float* qkv_w  = (const float*)d_in[1];
    const float* qkv_b  = (const float*)d_in[2];
    const float* out_w  = (const float*)d_in[3];
    const float* out_b  = (const float*)d_in[4];
    const float* pre_g  = (const float*)d_in[5];
    const float* pre_b  = (const float*)d_in[6];
    const float* lcm_g  = (const float*)d_in[7];
    const float* lcm_b  = (const float*)d_in[8];
    const float* ci_w   = (const float*)d_in[9];
    const float* ci_b   = (const float*)d_in[10];
    const float* bn_g   = (const float*)d_in[11];
    const float* bn_b   = (const float*)d_in[12];
    const float* co_w   = (const float*)d_in[13];
    const float* co_b   = (const float*)d_in[14];
    float* out = (float*)d_out;

    __half *p_normedh, *p_qkvh, *p_attnh, *p_wqkvTh, *p_woutTh;
    float *p_attnproj, *p_mu, *p_rinv;
    cudaGetSymbolAddress((void**)&p_normedh,  g_normedh);
    cudaGetSymbolAddress((void**)&p_qkvh,     g_qkvh);
    cudaGetSymbolAddress((void**)&p_attnh,    g_attnh);
    cudaGetSymbolAddress((void**)&p_attnproj, g_attnproj);
    cudaGetSymbolAddress((void**)&p_mu,       g_mu);
    cudaGetSymbolAddress((void**)&p_rinv,     g_rinv);
    cudaGetSymbolAddress((void**)&p_wqkvTh,   g_wqkvTh);
    cudaGetSymbolAddress((void**)&p_woutTh,   g_woutTh);

    // 1. merged weight transpose ([K,N] -> [N,K], fp16)
    transpose_kernel<<<dim3(64, 16), dim3(32,8)>>>(qkv_w, out_w, p_wqkvTh, p_woutTh);
    // 2. zero accumulators
    zero_kernel<<<(BB*HEADS*HD*HD + 255) / 256, 256>>>();
    // 3. pre-layernorm -> fp16
    ln_kernel<<<NTOK, 128>>>(x, pre_g, pre_b, p_normedh);
    // 4. qkv gemm (mma.sync fp16 + ldmatrix) + relu on q,k cols [0,1024)
    gemm_mma_kernel<__half><<<dim3(1536/128, NTOK/128), 256>>>(
        p_normedh, p_wqkvTh, qkv_b, p_qkvh, 1536, 1024);
    // 5. kv outer-product + ksum
    kv_kernel<<<dim3(BB*HEADS, 16), 256>>>(p_qkvh);
    // 6. attention apply -> fp16
    attn_kernel<<<dim3(BB*HEADS, 128), 256>>>(p_qkvh, p_attnh);
    // 7. output projection (mma.sync fp16) -> f32
    gemm_mma_kernel<float><<<dim3(CC/128, NTOK/128), 256>>>(
        p_attnh, p_woutTh, out_b, p_attnproj, 512, 0);
    // 8. LN2 stats (per-token mu, rinv)
    ln_stats_kernel<<<NTOK, 128>>>(p_attnproj, p_mu, p_rinv);
    // 9. conv1 (LN2-apply fused) + gelu + bn stats
    conv1_kernel<<<dim3(64, CC/32, BB), 256>>>(p_attnproj, ci_w, ci_b, lcm_g, lcm_b);
    // 10. bn apply + conv2 + residual sum -> out
    conv2_kernel<<<dim3(64, CC/32, BB), 256>>>(x, co_w, co_b, bn_g, bn_b, out);
}

// round 11
// speedup vs baseline: 1.1337x; 1.1337x over previous
#include <cuda_runtime.h>
#include <cuda_fp16.h>
#include <math.h>
#include <cstdint>

#define BB    8
#define NN    4096
#define CC    512
#define NTOK  (BB*NN)        // 32768 tokens
#define HEADS 8
#define HD    64
#define HH    64
#define WW    64
#define EPSF  1e-5f
#define CLAMPF 100.0f

// ---------------- scratch (static device globals; no runtime alloc) ----------
__device__ __half g_normedh[NTOK*CC];              // 32 MB (GEMM1 A)
__device__ __half g_qkvh[(size_t)NTOK*3*CC];       // 96 MB (GEMM1 out, fp16)
__device__ __half g_attnh[NTOK*CC];                // 32 MB (GEMM2 A)
__device__ __half g_attnproj[NTOK*CC];             // 32 MB (GEMM2 out, fp16)
__device__ __half g_y[NTOK*CC];                    // 32 MB (conv1 out, fp16)
__device__ float g_mu[NTOK];                       // LN2 per-token mean
__device__ float g_rinv[NTOK];                     // LN2 per-token 1/std
__device__ float g_kv[BB*HEADS*HD*HD];
__device__ float g_ksum[BB*HEADS*HD];
__device__ float g_sum[CC];
__device__ float g_sumsq[CC];
__device__ __half g_wqkvTh[3*CC*CC];               // [1536,512] fp16 transposed
__device__ __half g_woutTh[CC*CC];                 // [512,512]  fp16 transposed

// ============================ PTX helpers ====================================
__device__ __forceinline__ uint32_t smem_u32(const void* p){
    uint32_t a;
    asm("{ .reg .u64 t; cvta.to.shared.u64 t, %1; cvt.u32.u64 %0, t; }"
        : "=r"(a) : "l"(p));
    return a;
}
__device__ __forceinline__ void cpa16(uint32_t dst, const void* src){
    asm volatile("cp.async.ca.shared.global [%0], [%1], 16;"
                 :: "r"(dst), "l"(src) : "memory");
}
__device__ __forceinline__ void cpa_commit(){
    asm volatile("cp.async.commit_group;" ::: "memory");
}
template<int N> __device__ __forceinline__ void cpa_wait(){
    asm volatile("cp.async.wait_group %0;" :: "n"(N) : "memory");
}
__device__ __forceinline__ void mma_f16(float* d, const uint32_t* a, const uint32_t* b){
    asm volatile("mma.sync.aligned.m16n8k16.row.col.f32.f16.f16.f32 "
        "{%0,%1,%2,%3}, {%4,%5,%6,%7}, {%8,%9}, {%0,%1,%2,%3};"
        : "+f"(d[0]), "+f"(d[1]), "+f"(d[2]), "+f"(d[3])
        : "r"(a[0]), "r"(a[1]), "r"(a[2]), "r"(a[3]), "r"(b[0]), "r"(b[1]));
}
__device__ __forceinline__ void ldsm4(uint32_t& r0, uint32_t& r1,
                                      uint32_t& r2, uint32_t& r3, uint32_t addr){
    asm volatile("ldmatrix.sync.aligned.m8n8.x4.shared.b16 {%0,%1,%2,%3}, [%4];"
        : "=r"(r0), "=r"(r1), "=r"(r2), "=r"(r3) : "r"(addr));
}

// ============================ mma.sync fp16 GEMM =============================
// D[M,Nn] = A[M,512] @ Bt[Nn,512]^T + bias, relu on cols < nrelu.
// CTA 128x128, 8 warps (4m x 2n), warp tile 32x64. BK=32, ldmatrix, 2 CTA/SM.
#define GK    512
#define GBK   32
#define KPADH 40              // halves per row (80B stride; conflict-free LDSM)
#define NKT   (GK/GBK)        // 16 k-tiles

template<typename OUT>
__global__ void __launch_bounds__(256, 2)
gemm_mma_kernel(const __half* __restrict__ A,
                const __half* __restrict__ Bt,
                const float* __restrict__ bias, OUT* __restrict__ Cout,
                int Nn, int nrelu)
{
    __shared__ __half As[2][128][KPADH];
    __shared__ __half Bs[2][128][KPADH];
    int tid = threadIdx.x;
    int wid = tid >> 5, lane = tid & 31;
    int gid = lane >> 2, tig = lane & 3;
    int warpM = (wid >> 1) * 32;
    int warpN = (wid & 1) * 64;
    int row0 = blockIdx.y * 128, col0 = blockIdx.x * 128;
    const __half* Ab = A  + (size_t)row0 * GK;
    const __half* Bb = Bt + (size_t)col0 * GK;

    int q0 = tid, q1 = tid + 256;
    int r0 = q0 >> 2, c0 = q0 & 3;
    int r1 = q1 >> 2, c1 = q1 & 3;
    uint32_t sA0 = smem_u32(&As[0][r0][0]) + c0 * 16;
    uint32_t sA1 = smem_u32(&As[0][r1][0]) + c1 * 16;
    uint32_t sB0 = smem_u32(&Bs[0][r0][0]) + c0 * 16;
    uint32_t sB1 = smem_u32(&Bs[0][r1][0]) + c1 * 16;
    const uint32_t stageOff = 128 * KPADH * 2;

    // ldmatrix base addresses (per-lane)
    int aRow = warpM + (lane & 15);
    int aCol = (lane >> 4) * 8;
    int bRow = warpN + (lane >> 4) * 8 + (lane & 7);
    int bCol = ((lane >> 3) & 1) * 8;
    uint32_t aBase = smem_u32(&As[0][aRow][aCol]);
    uint32_t bBase = smem_u32(&Bs[0][bRow][bCol]);

    float acc[2][8][4];
    #pragma unroll
    for (int mi = 0; mi < 2; mi++)
        #pragma unroll
        for (int ni = 0; ni < 8; ni++)
            #pragma unroll
            for (int r = 0; r < 4; r++) acc[mi][ni][r] = 0.f;

    auto load_tile = [&](int t, int b){
        int k0 = t * GBK;
        uint32_t so = b * stageOff;
        cpa16(sA0 + so, Ab + (size_t)r0 * GK + k0 + c0 * 8);
        cpa16(sA1 + so, Ab + (size_t)r1 * GK + k0 + c1 * 8);
        cpa16(sB0 + so, Bb + (size_t)r0 * GK + k0 + c0 * 8);
        cpa16(sB1 + so, Bb + (size_t)r1 * GK + k0 + c1 * 8);
    };

    load_tile(0, 0);
    cpa_commit();

    for (int t = 0; t < NKT; t++){
        int cb = t & 1;
        if (t + 1 < NKT) load_tile(t + 1, (t + 1) & 1);
        cpa_commit();
        cpa_wait<1>();
        __syncthreads();
        uint32_t stage = cb * stageOff;
        #pragma unroll
        for (int ks = 0; ks < 2; ks++){
            int k0 = ks * 16;
            uint32_t a[2][4], bfr[8][2];
            #pragma unroll
            for (int mi = 0; mi < 2; mi++){
                uint32_t ad = aBase + stage + (mi * 16 * KPADH + k0) * 2;
                ldsm4(a[mi][0], a[mi][1], a[mi][2], a[mi][3], ad);
            }
            #pragma unroll
            for (int p = 0; p < 4; p++){
                uint32_t bd = bBase + stage + (p * 16 * KPADH + k0) * 2;
                ldsm4(bfr[2*p][0], bfr[2*p][1], bfr[2*p+1][0], bfr[2*p+1][1], bd);
            }
            #pragma unroll
            for (int mi = 0; mi < 2; mi++)
                #pragma unroll
                for (int ni = 0; ni < 8; ni++)
                    mma_f16(acc[mi][ni], a[mi], bfr[ni]);
        }
        __syncthreads();
    }

    // epilogue: bias + optional relu
    #pragma unroll
    for (int mi = 0; mi < 2; mi++){
        #pragma unroll
        for (int rr = 0; rr < 2; rr++){
            int r = row0 + warpM + mi * 16 + rr * 8 + gid;
            #pragma unroll
            for (int ni = 0; ni < 8; ni++){
                int c = col0 + warpN + ni * 8 + tig * 2;
                float ox = acc[mi][ni][rr * 2 + 0] + bias[c + 0];
                float oy = acc[mi][ni][rr * 2 + 1] + bias[c + 1];
                if (c < nrelu){
                    ox = fmaxf(ox, 0.f);
                    oy = fmaxf(oy, 0.f);
                }
                if constexpr (sizeof(OUT) == 4) {
                    float2 o{ox, oy};
                    *(float2*)((float*)Cout + (size_t)r * Nn + c) = o;
                } else {
                    __half2 o{__float2half(ox), __float2half(oy)};
                    *(__half2*)((__half*)Cout + (size_t)r * Nn + c) = o;
                }
            }
        }
    }
}

// ---------------- merged weight transpose -> fp16 ----------------------------
__global__ void transpose_kernel(const float* __restrict__ qkvw,
                                 const float* __restrict__ outw,
                                 __half* __restrict__ qkvT,
                                 __half* __restrict__ outT)
{
    __shared__ float tile[32][33];
    const float* in; __half* outp; int Cc, bxi;
    if (blockIdx.x < 48){ in = qkvw; outp = qkvT; Cc = 1536; bxi = blockIdx.x; }
    else                { in = outw; outp = outT; Cc = 512;  bxi = blockIdx.x - 48; }
    int bx = bxi * 32, by = blockIdx.y * 32;
    int tx = threadIdx.x, ty = threadIdx.y;   // 32 x 8
    #pragma unroll
    for (int i = 0; i < 32; i += 8)
        tile[ty + i][tx] = in[(size_t)(by + ty + i) * Cc + bx + tx];
    __syncthreads();
    #pragma unroll
    for (int i = 0; i < 32; i += 8)
        outp[(size_t)(bx + ty + i) * 512 + by + tx] = __float2half(tile[tx][ty + i]);
}

// ---------------- layernorm over C=512 -> fp16 -------------------------------
__global__ void ln_kernel(const float* __restrict__ in,
                          const float* __restrict__ gamma,
                          const float* __restrict__ beta,
                          __half* __restrict__ out)
{
    int token = blockIdx.x;
    const float4* row = (const float4*)(in + (size_t)token * CC);
    int tid = threadIdx.x;
    float4 v = row[tid];
    float s  = v.x + v.y + v.z + v.w;
    float sq = v.x*v.x + v.y*v.y + v.z*v.z + v.w*v.w;
    #pragma unroll
    for (int o = 16; o; o >>= 1) {
        s  += __shfl_xor_sync(0xffffffffu, s,  o);
        sq += __shfl_xor_sync(0xffffffffu, sq, o);
    }
    __shared__ float ss[4], ssq[4];
    if ((tid & 31) == 0) { ss[tid >> 5] = s; ssq[tid >> 5] = sq; }
    __syncthreads();
    float ts = ss[0] + ss[1] + ss[2] + ss[3];
    float tq = ssq[0] + ssq[1] + ssq[2] + ssq[3];
    float mean = ts * (1.0f / CC);
    float var  = tq * (1.0f / CC) - mean * mean;
    float inv  = rsqrtf(var + EPSF);
    float4 g4 = ((const float4*)gamma)[tid];
    float4 b4 = ((const float4*)beta)[tid];
    __half2 p0{__float2half((v.x - mean) * inv * g4.x + b4.x),
               __float2half((v.y - mean) * inv * g4.y + b4.y)};
    __half2 p1{__float2half((v.z - mean) * inv * g4.z + b4.z),
               __float2half((v.w - mean) * inv * g4.w + b4.w)};
    uint2 pk;
    pk.x = *(uint32_t*)&p0;
    pk.y = *(uint32_t*)&p1;
    ((uint2*)(out + (size_t)token * CC))[tid] = pk;
}

// ---------------- LN2 stats from fp16 attnproj -------------------------------
__global__ void ln_stats_kernel(const __half* __restrict__ in,
                                float* __restrict__ mu, float* __restrict__ rinv)
{
    int token = blockIdx.x;
    const uint2* row = (const uint2*)(in + (size_t)token * CC);  // 4 halves
    int tid = threadIdx.x;
    uint2 pk = row[tid];
    __half2 h0 = *(__half2*)&pk.x;
    __half2 h1 = *(__half2*)&pk.y;
    float2 a = __half22float2(h0);
    float2 b = __half22float2(h1);
    float s  = a.x + a.y + b.x + b.y;
    float sq = a.x*a.x + a.y*a.y + b.x*b.x + b.y*b.y;
    #pragma unroll
    for (int o = 16; o; o >>= 1) {
        s  += __shfl_xor_sync(0xffffffffu, s,  o);
        sq += __shfl_xor_sync(0xffffffffu, sq, o);
    }
    __shared__ float ss[4], ssq[4];
    if ((tid & 31) == 0) { ss[tid >> 5] = s; ssq[tid >> 5] = sq; }
    __syncthreads();
    if (tid == 0){
        float ts = ss[0] + ss[1] + ss[2] + ss[3];
        float tq = ssq[0] + ssq[1] + ssq[2] + ssq[3];
        float mean = ts * (1.0f / CC);
        float var  = tq * (1.0f / CC) - mean * mean;
        mu[token]   = mean;
        rinv[token] = rsqrtf(var + EPSF);
    }
}

// ---------------- zero scratch accumulators ---------------------------------
__global__ void zero_kernel()
{
    int i = blockIdx.x * blockDim.x + threadIdx.x;
    if (i < BB*HEADS*HD*HD) g_kv[i] = 0.f;
    if (i < BB*HEADS*HD)    g_ksum[i] = 0.f;
    if (i < CC)           { g_sum[i] = 0.f; g_sumsq[i] = 0.f; }
}

// ---------------- kv = k^T v per (b,h); ksum = sum_n k (fp16 in) -------------
__global__ __launch_bounds__(256)
void kv_kernel(const __half* __restrict__ qkv)
{
    int bh = blockIdx.x;
    int b = bh >> 3, h = bh & 7;
    const __half* kbase = qkv + (size_t)(b*NN)*1536 +  512 + h*64;
    const __half* vbase = qkv + (size_t)(b*NN)*1536 + 1024 + h*64;
    __shared__ float ks[64][64];
    __shared__ float vs[64][64];
    int tid = threadIdx.x;
    int lr  = tid >> 3;
    int lc8 = (tid & 7) * 8;
    int ty = tid >> 4, tx = tid & 15;
    float acc[4][4];
    #pragma unroll
    for (int i = 0; i < 4; i++)
        #pragma unroll
        for (int j = 0; j < 4; j++) acc[i][j] = 0.f;
    float ksum8[8];
    #pragma unroll
    for (int j = 0; j < 8; j++) ksum8[j] = 0.f;
    int n0 = blockIdx.y * 256;
    for (int s = 0; s < 4; s++) {
        int base = n0 + s * 64;
        #pragma unroll
        for (int p = 0; p < 2; p++) {
            int r = p * 32 + lr;
            uint4 kk = *(const uint4*)(kbase + (size_t)(base + r) * 1536 + lc8);
            uint4 vv = *(const uint4*)(vbase + (size_t)(base + r) * 1536 + lc8);
            const __half2* kh = (const __half2*)&kk;
            const __half2* vh = (const __half2*)&vv;
            #pragma unroll
            for (int j = 0; j < 4; j++){
                float2 kf = __half22float2(kh[j]);
                float2 vf = __half22float2(vh[j]);
                ks[r][lc8 + 2*j    ] = kf.x;
                ks[r][lc8 + 2*j + 1] = kf.y;
                vs[r][lc8 + 2*j    ] = vf.x;
                vs[r][lc8 + 2*j + 1] = vf.y;
                ksum8[2*j]     += kf.x;
                ksum8[2*j + 1] += kf.y;
            }
        }
        __syncthreads();
        #pragma unroll 8
        for (int n = 0; n < 64; n++) {
            float rk[4], rv[4];
            *(float4*)rk = *(const float4*)&ks[n][ty * 4];
            *(float4*)rv = *(const float4*)&vs[n][tx * 4];
            #pragma unroll
            for (int i = 0; i < 4; i++)
                #pragma unroll
                for (int j = 0; j < 4; j++)
                    acc[i][j] += rk[i] * rv[j];
        }
        __syncthreads();
    }
    float* kvout = g_kv + bh * 4096;
    #pragma unroll
    for (int i = 0; i < 4; i++)
        #pragma unroll
        for (int j = 0; j < 4; j++)
            atomicAdd(&kvout[(ty*4 + i) * 64 + tx*4 + j], acc[i][j]);
    #pragma unroll
    for (int j = 0; j < 8; j++){
        ksum8[j] += __shfl_xor_sync(0xffffffffu, ksum8[j], 8);
        ksum8[j] += __shfl_xor_sync(0xffffffffu, ksum8[j], 16);
    }
    if ((tid & 31) < 8){
        #pragma unroll
        for (int j = 0; j < 8; j++)
            atomicAdd(&g_ksum[bh * 64 + lc8 + j], ksum8[j]);
    }
}

// ---------------- attn: warp-autonomous, no inner-loop syncs -----------------
// grid (64 bh, 16), block 256 = 8 warps; 32 tokens per warp sequentially.
__global__ __launch_bounds__(256)
void attn_kernel(const __half* __restrict__ qkv, __half* __restrict__ attn)
{
    int bh = blockIdx.x;
    int b = bh >> 3, h = bh & 7;
    __shared__ float kvs[64][64];
    __shared__ float norms[64];
    int tid = threadIdx.x;
    for (int i = tid; i < 4096; i += 256)
        kvs[i >> 6][i & 63] = g_kv[bh * 4096 + i];
    if (tid < 64) norms[tid] = fmaxf(g_ksum[bh * 64 + tid], CLAMPF);
    __syncthreads();
    int wid = tid >> 5, lane = tid & 31;
    const __half* qbase = qkv + (size_t)(b*NN)*1536 + h*64;
    int nbase = blockIdx.y * 256 + wid * 32;
    for (int it = 0; it < 32; it++) {
        int n = nbase + it;
        __half2 q2 = *(const __half2*)(qbase + (size_t)n * 1536 + 2*lane);
        float2 qf = __half22float2(q2);
        float acc0 = 0.f, acc1 = 0.f, den = 0.f;
        #pragma unroll
        for (int d = 0; d < 64; d += 2){
            float qa = __shfl_sync(0xffffffffu, qf.x, d >> 1);
            float qb = __shfl_sync(0xffffffffu, qf.y, d >> 1);
            acc0 += qa * kvs[d][lane];
            acc1 += qa * kvs[d][lane + 32];
            den  += qa * norms[d];
            acc0 += qb * kvs[d+1][lane];
            acc1 += qb * kvs[d+1][lane + 32];
            den  += qb * norms[d+1];
        }
        float inv = 1.0f / fmaxf(den, CLAMPF);
        __half* orow = attn + (size_t)(b*NN + n) * CC + h*64;
        orow[lane]      = __float2half(acc0 * inv);
        orow[lane + 32] = __float2half(acc1 * inv);
    }
}

// ---------------- conv1: fused LN2-apply + dw7x7 + gelu + bn stats -----------
__global__ __launch_bounds__(256)
void conv1_kernel(const __half* __restrict__ ap, const float* __restrict__ cw,
                  const float* __restrict__ cb, const float* __restrict__ lg,
                  const float* __restrict__ lb)
{
    int b  = blockIdx.z;
    int c0 = blockIdx.y * 32;
    int h0 = (blockIdx.x >> 3) * 8;
    int w0 = (blockIdx.x & 7) * 8;
    __shared__ float ins[14][14][32];
    __shared__ float ws[32][49];
    __shared__ float sg[32], sb[32];
    __shared__ float rsum[8][32], rsq[8][32];
    int tid = threadIdx.x;
    if (tid < 32){ sg[tid] = lg[c0 + tid]; sb[tid] = lb[c0 + tid]; }
    for (int i = tid; i < 32 * 49; i += 256)
        ws[i / 49][i % 49] = cw[(c0 + i / 49) * 49 + (i % 49)];
    __syncthreads();
    for (int i = tid; i < 14 * 14 * 32; i += 256) {
        int ic = i & 31; int pos = i >> 5;
        int iw = pos % 14, ih = pos / 14;
        int gh = h0 + ih - 3, gw = w0 + iw - 3;
        float v = 0.f;
        if (gh >= 0 && gh < HH && gw >= 0 && gw < WW){
            size_t tok = (size_t)(b*NN) + gh*WW + gw;
            float a = __half2float(ap[tok * CC + c0 + ic]);
            v = (a - g_mu[tok]) * g_rinv[tok] * sg[ic] + sb[ic];
        }
        ins[ih][iw][ic] = v;
    }
    __syncthreads();
    int oc = tid & 31;
    int ow = tid >> 5;
    float wr[49];
    #pragma unroll
    for (int j = 0; j < 49; j++) wr[j] = ws[oc][j];
    float bias = cb[c0 + oc];
    float acc[8];
    #pragma unroll
    for (int oh = 0; oh < 8; oh++) acc[oh] = bias;
    #pragma unroll
    for (int ih = 0; ih < 14; ih++){
        float v[7];
        #pragma unroll
        for (int dw = 0; dw < 7; dw++) v[dw] = ins[ih][ow + dw][oc];
        #pragma unroll
        for (int oh = 0; oh < 8; oh++){
            int dh = ih - oh;
            if (dh >= 0 && dh < 7){
                #pragma unroll
                for (int dw = 0; dw < 7; dw++)
                    acc[oh] += v[dw] * wr[dh * 7 + dw];
            }
        }
    }
    float psum = 0.f, psq = 0.f;
    #pragma unroll
    for (int oh = 0; oh < 8; oh++){
        float yv = acc[oh] * normcdff(acc[oh]);
        g_y[((size_t)(b*NN) + (h0+oh)*WW + (w0+ow)) * CC + c0 + oc] = __float2half(yv);
        psum += yv; psq += yv * yv;
    }
    rsum[ow][oc] = psum; rsq[ow][oc] = psq;
    __syncthreads();
    if (tid < 32) {
        float s = 0.f, q = 0.f;
        #pragma unroll
        for (int i = 0; i < 8; i++) { s += rsum[i][tid]; q += rsq[i][tid]; }
        atomicAdd(&g_sum[c0 + tid], s);
        atomicAdd(&g_sumsq[c0 + tid], q);
    }
}

// ---------------- conv2: BN-apply + depthwise 7x7 + triple residual ----------
__global__ __launch_bounds__(256)
void conv2_kernel(const float* __restrict__ x, const float* __restrict__ cw,
                  const float* __restrict__ cb, const float* __restrict__ bng,
                  const float* __restrict__ bnb, float* __restrict__ out)
{
    int b  = blockIdx.z;
    int c0 = blockIdx.y * 32;
    int h0 = (blockIdx.x >> 3) * 8;
    int w0 = (blockIdx.x & 7) * 8;
    __shared__ float ins[14][14][32];
    __shared__ float ws[32][49];
    __shared__ float scs[32], shs[32];
    int tid = threadIdx.x;
    if (tid < 32) {
        int c = c0 + tid;
        float m   = g_sum[c]   * (1.0f / (float)NTOK);
        float var = g_sumsq[c] * (1.0f / (float)NTOK) - m * m;
        float inv = rsqrtf(var + EPSF);
        float sc = bng[c] * inv;
        scs[tid] = sc;
        shs[tid] = bnb[c] - m * sc;
    }
    for (int i = tid; i < 32 * 49; i += 256)
        ws[i / 49][i % 49] = cw[(c0 + i / 49) * 49 + (i % 49)];
    __syncthreads();
    for (int i = tid; i < 14 * 14 * 32; i += 256) {
        int ic = i & 31; int pos = i >> 5;
        int iw = pos % 14, ih = pos / 14;
        int gh = h0 + ih - 3, gw = w0 + iw - 3;
        float v = 0.f;
        if (gh >= 0 && gh < HH && gw >= 0 && gw < WW)
            v = __half2float(g_y[((size_t)(b*NN) + gh*WW + gw) * CC + c0 + ic])
                * scs[ic] + shs[ic];
        ins[ih][iw][ic] = v;
    }
    __syncthreads();
    int oc = tid & 31;
    int ow = tid >> 5;
    float wr[49];
    #pragma unroll
    for (int j = 0; j < 49; j++) wr[j] = ws[oc][j];
    float bias = cb[c0 + oc];
    float acc[8];
    #pragma unroll
    for (int oh = 0; oh < 8; oh++) acc[oh] = bias;
    #pragma unroll
    for (int ih = 0; ih < 14; ih++){
        float v[7];
        #pragma unroll
        for (int dw = 0; dw < 7; dw++) v[dw] = ins[ih][ow + dw][oc];
        #pragma unroll
        for (int oh = 0; oh < 8; oh++){
            int dh = ih - oh;
            if (dh >= 0 && dh < 7){
                #pragma unroll
                for (int dw = 0; dw < 7; dw++)
                    acc[oh] += v[dw] * wr[dh * 7 + dw];
            }
        }
    }
    #pragma unroll
    for (int oh = 0; oh < 8; oh++){
        size_t idx = ((size_t)(b*NN) + (h0+oh)*WW + (w0+ow)) * CC + c0 + oc;
        out[idx] = x[idx] + __half2float(g_attnproj[idx]) + acc[oh];
    }
}

// ---------------- launch ----------------------------------------------------
extern "C" void kernel_launch(void* const* d_in, const int* in_sizes, int n_in,
                              void* d_out, int out_size)
{
    const float* x      = (const float*)d_in[0];
    const float* qkv_w  = (const float*)d_in[1];
    const float* qkv_b  = (const float*)d_in[2];
    const float* out_w  = (const float*)d_in[3];
    const float* out_b  = (const float*)d_in[4];
    const float* pre_g  = (const float*)d_in[5];
    const float* pre_b  = (const float*)d_in[6];
    const float* lcm_g  = (const float*)d_in[7];
    const float* lcm_b  = (const float*)d_in[8];
    const float* ci_w   = (const float*)d_in[9];
    const float* ci_b   = (const float*)d_in[10];
    const float* bn_g   = (const float*)d_in[11];
    const float* bn_b   = (const float*)d_in[12];
    const float* co_w   = (const float*)d_in[13];
    const float* co_b   = (const float*)d_in[14];
    float* out = (float*)d_out;

    __half *p_normedh, *p_qkvh, *p_attnh, *p_attnproj, *p_wqkvTh, *p_woutTh;
    float *p_mu, *p_rinv;
    cudaGetSymbolAddress((void**)&p_normedh,  g_normedh);
    cudaGetSymbolAddress((void**)&p_qkvh,     g_qkvh);
    cudaGetSymbolAddress((void**)&p_attnh,    g_attnh);
    cudaGetSymbolAddress((void**)&p_attnproj, g_attnproj);
    cudaGetSymbolAddress((void**)&p_mu,       g_mu);
    cudaGetSymbolAddress((void**)&p_rinv,     g_rinv);
    cudaGetSymbolAddress((void**)&p_wqkvTh,   g_wqkvTh);
    cudaGetSymbolAddress((void**)&p_woutTh,   g_woutTh);

    // 1. merged weight transpose ([K,N] -> [N,K], fp16)
    transpose_kernel<<<dim3(64, 16), dim3(32,8)>>>(qkv_w, out_w, p_wqkvTh, p_woutTh);
    // 2. zero accumulators
    zero_kernel<<<(BB*HEADS*HD*HD + 255) / 256, 256>>>();
    // 3. pre-layernorm -> fp16
    ln_kernel<<<NTOK, 128>>>(x, pre_g, pre_b, p_normedh);
    // 4. qkv gemm (mma.sync fp16 + ldmatrix, 2 CTA/SM) + relu on cols [0,1024)
    gemm_mma_kernel<__half><<<dim3(1536/128, NTOK/128), 256>>>(
        p_normedh, p_wqkvTh, qkv_b, p_qkvh, 1536, 1024);
    // 5. kv outer-product + ksum
    kv_kernel<<<dim3(BB*HEADS, 16), 256>>>(p_qkvh);
    // 6. attention apply -> fp16 (warp-autonomous)
    attn_kernel<<<dim3(BB*HEADS, 16), 256>>>(p_qkvh, p_attnh);
    // 7. output projection (mma.sync fp16) -> fp16
    gemm_mma_kernel<__half><<<dim3(CC/128, NTOK/128), 256>>>(
        p_attnh, p_woutTh, out_b, p_attnproj, 512, 0);
    // 8. LN2 stats (per-token mu, rinv) from fp16
    ln_stats_kernel<<<NTOK, 128>>>(p_attnproj, p_mu, p_rinv);
    // 9. conv1 (LN2-apply fused) + gelu + bn stats -> fp16 y
    conv1_kernel<<<dim3(64, CC/32, BB), 256>>>(p_attnproj, ci_w, ci_b, lcm_g, lcm_b);
    // 10. bn apply + conv2 + triple residual -> out
    conv2_kernel<<<dim3(64, CC/32, BB), 256>>>(x, co_w, co_b, bn_g, bn_b, out);
}

// round 13
// speedup vs baseline: 1.1689x; 1.0310x over previous
#include <cuda_runtime.h>
#include <cuda_fp16.h>
#include <math.h>
#include <cstdint>

#define BB    8
#define NN    4096
#define CC    512
#define NTOK  (BB*NN)        // 32768 tokens
#define HEADS 8
#define HD    64
#define HH    64
#define WW    64
#define EPSF  1e-5f
#define CLAMPF 100.0f

// ---------------- scratch (static device globals; no runtime alloc) ----------
__device__ __half g_normedh[NTOK*CC];              // 32 MB (GEMM1 A)
__device__ __half g_qkvh[(size_t)NTOK*3*CC];       // 96 MB (GEMM1 out, fp16)
__device__ __half g_attnh[NTOK*CC];                // 32 MB (GEMM2 A)
__device__ __half g_attnproj[NTOK*CC];             // 32 MB (GEMM2 out, fp16)
__device__ __half g_y[NTOK*CC];                    // 32 MB (conv1 out, fp16)
__device__ float g_mu[NTOK];                       // LN2 per-token mean
__device__ float g_rinv[NTOK];                     // LN2 per-token 1/std
__device__ float g_musum[NTOK];                    // LN2 partial row sums
__device__ float g_sqsum[NTOK];
__device__ float g_kv[BB*HEADS*HD*HD];
__device__ float g_ksum[BB*HEADS*HD];
__device__ float g_sum[CC];
__device__ float g_sumsq[CC];
__device__ __half g_wqkvTh[3*CC*CC];               // [1536,512] fp16 transposed
__device__ __half g_woutTh[CC*CC];                 // [512,512]  fp16 transposed

// ============================ PTX helpers ====================================
__device__ __forceinline__ uint32_t smem_u32(const void* p){
    uint32_t a;
    asm("{ .reg .u64 t; cvta.to.shared.u64 t, %1; cvt.u32.u64 %0, t; }"
        : "=r"(a) : "l"(p));
    return a;
}
__device__ __forceinline__ void cpa16(uint32_t dst, const void* src){
    asm volatile("cp.async.ca.shared.global [%0], [%1], 16;"
                 :: "r"(dst), "l"(src) : "memory");
}
__device__ __forceinline__ void cpa_commit(){
    asm volatile("cp.async.commit_group;" ::: "memory");
}
template<int N> __device__ __forceinline__ void cpa_wait(){
    asm volatile("cp.async.wait_group %0;" :: "n"(N) : "memory");
}
__device__ __forceinline__ void mma_f16(float* d, const uint32_t* a, const uint32_t* b){
    asm volatile("mma.sync.aligned.m16n8k16.row.col.f32.f16.f16.f32 "
        "{%0,%1,%2,%3}, {%4,%5,%6,%7}, {%8,%9}, {%0,%1,%2,%3};"
        : "+f"(d[0]), "+f"(d[1]), "+f"(d[2]), "+f"(d[3])
        : "r"(a[0]), "r"(a[1]), "r"(a[2]), "r"(a[3]), "r"(b[0]), "r"(b[1]));
}
__device__ __forceinline__ void ldsm4(uint32_t& r0, uint32_t& r1,
                                      uint32_t& r2, uint32_t& r3, uint32_t addr){
    asm volatile("ldmatrix.sync.aligned.m8n8.x4.shared.b16 {%0,%1,%2,%3}, [%4];"
        : "=r"(r0), "=r"(r1), "=r"(r2), "=r"(r3) : "r"(addr));
}

// ============================ mma.sync fp16 GEMM =============================
// D[M,Nn] = A[M,512] @ Bt[Nn,512]^T + bias, relu on cols < nrelu.
// CTA 128x128, 8 warps (4m x 2n), warp tile 32x64. BK=32, ldmatrix,
// 3-stage cp.async pipeline with a single __syncthreads per K-tile, 2 CTA/SM.
// STATS: accumulate per-row sum/sumsq (for fused LN stats) via atomics.
#define GK    512
#define GBK   32
#define KPADH 40              // halves per row (80B stride; conflict-free LDSM)
#define NKT   (GK/GBK)        // 16 k-tiles
#define ROWB  (KPADH*2)       // 80 bytes per smem row
#define ASTG  (128*ROWB)      // 10240 bytes per stage per operand
#define GSMEM (6*ASTG)        // 61440 bytes total (3 stages x A,B)

template<typename OUT, bool STATS>
__global__ void __launch_bounds__(256, 2)
gemm_mma_kernel(const __half* __restrict__ A,
                const __half* __restrict__ Bt,
                const float* __restrict__ bias, OUT* __restrict__ Cout,
                int Nn, int nrelu)
{
    extern __shared__ __half dsm[];
    __shared__ float ssum[128], ssq[128];
    uint32_t base = smem_u32(dsm);
    const uint32_t BOFF = 3 * ASTG;
    int tid = threadIdx.x;
    int wid = tid >> 5, lane = tid & 31;
    int gid = lane >> 2, tig = lane & 3;
    int warpM = (wid >> 1) * 32;
    int warpN = (wid & 1) * 64;
    int row0 = blockIdx.y * 128, col0 = blockIdx.x * 128;
    const __half* Ab = A  + (size_t)row0 * GK;
    const __half* Bb = Bt + (size_t)col0 * GK;

    if (STATS && tid < 128){ ssum[tid] = 0.f; ssq[tid] = 0.f; }

    // cp.async: 512 16B-chunks per operand per stage; 2 chunks each per thread
    int r0i = tid >> 2,          c0i = tid & 3;
    int r1i = (tid + 256) >> 2,  c1i = c0i;
    uint32_t aoff0 = (uint32_t)(r0i * ROWB + c0i * 16);
    uint32_t aoff1 = (uint32_t)(r1i * ROWB + c1i * 16);

    // ldmatrix per-lane base offsets (within a stage)
    int aRow = warpM + (lane & 15);
    int aCol = (lane >> 4) * 8;
    int bRow = warpN + (lane >> 4) * 8 + (lane & 7);
    int bCol = ((lane >> 3) & 1) * 8;
    uint32_t aBase = (uint32_t)(aRow * ROWB + aCol * 2);
    uint32_t bBase = (uint32_t)(bRow * ROWB + bCol * 2);

    float acc[2][8][4];
    #pragma unroll
    for (int mi = 0; mi < 2; mi++)
        #pragma unroll
        for (int ni = 0; ni < 8; ni++)
            #pragma unroll
            for (int r = 0; r < 4; r++) acc[mi][ni][r] = 0.f;

    auto load_tile = [&](int t, int s){
        int k0 = t * GBK;
        uint32_t sa = base + s * ASTG;
        uint32_t sb = base + BOFF + s * ASTG;
        cpa16(sa + aoff0, Ab + (size_t)r0i * GK + k0 + c0i * 8);
        cpa16(sa + aoff1, Ab + (size_t)r1i * GK + k0 + c1i * 8);
        cpa16(sb + aoff0, Bb + (size_t)r0i * GK + k0 + c0i * 8);
        cpa16(sb + aoff1, Bb + (size_t)r1i * GK + k0 + c1i * 8);
    };

    load_tile(0, 0); cpa_commit();
    load_tile(1, 1); cpa_commit();

    for (int t = 0; t < NKT; t++){
        int s = t % 3;
        cpa_wait<1>();
        __syncthreads();
        if (t + 2 < NKT) load_tile(t + 2, (t + 2) % 3);
        cpa_commit();
        uint32_t sa = base + s * ASTG;
        uint32_t sb = base + BOFF + s * ASTG;
        #pragma unroll
        for (int ks = 0; ks < 2; ks++){
            int k0 = ks * 16;
            uint32_t a[2][4], bfr[8][2];
            #pragma unroll
            for (int mi = 0; mi < 2; mi++){
                uint32_t ad = sa + aBase + (uint32_t)(mi * 16 * ROWB + k0 * 2);
                ldsm4(a[mi][0], a[mi][1], a[mi][2], a[mi][3], ad);
            }
            #pragma unroll
            for (int p = 0; p < 4; p++){
                uint32_t bd = sb + bBase + (uint32_t)(p * 16 * ROWB + k0 * 2);
                ldsm4(bfr[2*p][0], bfr[2*p][1], bfr[2*p+1][0], bfr[2*p+1][1], bd);
            }
            #pragma unroll
            for (int mi = 0; mi < 2; mi++)
                #pragma unroll
                for (int ni = 0; ni < 8; ni++)
                    mma_f16(acc[mi][ni], a[mi], bfr[ni]);
        }
    }

    // epilogue: bias + optional relu (+ fused row stats)
    #pragma unroll
    for (int mi = 0; mi < 2; mi++){
        #pragma unroll
        for (int rr = 0; rr < 2; rr++){
            int rloc = warpM + mi * 16 + rr * 8 + gid;
            int r = row0 + rloc;
            float s = 0.f, sq = 0.f;
            #pragma unroll
            for (int ni = 0; ni < 8; ni++){
                int c = col0 + warpN + ni * 8 + tig * 2;
                float ox = acc[mi][ni][rr * 2 + 0] + bias[c + 0];
                float oy = acc[mi][ni][rr * 2 + 1] + bias[c + 1];
                if (c < nrelu){
                    ox = fmaxf(ox, 0.f);
                    oy = fmaxf(oy, 0.f);
                }
                if (STATS){
                    s  += ox + oy;
                    sq += ox * ox + oy * oy;
                }
                if constexpr (sizeof(OUT) == 4) {
                    float2 o{ox, oy};
                    *(float2*)((float*)Cout + (size_t)r * Nn + c) = o;
                } else {
                    __half2 o{__float2half(ox), __float2half(oy)};
                    *(__half2*)((__half*)Cout + (size_t)r * Nn + c) = o;
                }
            }
            if (STATS){
                s  += __shfl_xor_sync(0xffffffffu, s, 1);
                s  += __shfl_xor_sync(0xffffffffu, s, 2);
                sq += __shfl_xor_sync(0xffffffffu, sq, 1);
                sq += __shfl_xor_sync(0xffffffffu, sq, 2);
                if (tig == 0){
                    atomicAdd(&ssum[rloc], s);
                    atomicAdd(&ssq[rloc], sq);
                }
            }
        }
    }
    if (STATS){
        __syncthreads();
        if (tid < 128){
            atomicAdd(&g_musum[row0 + tid], ssum[tid]);
            atomicAdd(&g_sqsum[row0 + tid], ssq[tid]);
        }
    }
}

// ---------------- LN2 finalize: sums -> mu, rinv -----------------------------
__global__ void ln_fin_kernel()
{
    int i = blockIdx.x * blockDim.x + threadIdx.x;
    float mean = g_musum[i] * (1.0f / CC);
    float var  = g_sqsum[i] * (1.0f / CC) - mean * mean;
    g_mu[i]   = mean;
    g_rinv[i] = rsqrtf(var + EPSF);
}

// ---------------- merged weight transpose -> fp16 ----------------------------
__global__ void transpose_kernel(const float* __restrict__ qkvw,
                                 const float* __restrict__ outw,
                                 __half* __restrict__ qkvT,
                                 __half* __restrict__ outT)
{
    __shared__ float tile[32][33];
    const float* in; __half* outp; int Cc, bxi;
    if (blockIdx.x < 48){ in = qkvw; outp = qkvT; Cc = 1536; bxi = blockIdx.x; }
    else                { in = outw; outp = outT; Cc = 512;  bxi = blockIdx.x - 48; }
    int bx = bxi * 32, by = blockIdx.y * 32;
    int tx = threadIdx.x, ty = threadIdx.y;   // 32 x 8
    #pragma unroll
    for (int i = 0; i < 32; i += 8)
        tile[ty + i][tx] = in[(size_t)(by + ty + i) * Cc + bx + tx];
    __syncthreads();
    #pragma unroll
    for (int i = 0; i < 32; i += 8)
        outp[(size_t)(bx + ty + i) * 512 + by + tx] = __float2half(tile[tx][ty + i]);
}

// ---------------- layernorm over C=512 -> fp16 -------------------------------
__global__ void ln_kernel(const float* __restrict__ in,
                          const float* __restrict__ gamma,
                          const float* __restrict__ beta,
                          __half* __restrict__ out)
{
    int token = blockIdx.x;
    const float4* row = (const float4*)(in + (size_t)token * CC);
    int tid = threadIdx.x;
    float4 v = row[tid];
    float s  = v.x + v.y + v.z + v.w;
    float sq = v.x*v.x + v.y*v.y + v.z*v.z + v.w*v.w;
    #pragma unroll
    for (int o = 16; o; o >>= 1) {
        s  += __shfl_xor_sync(0xffffffffu, s,  o);
        sq += __shfl_xor_sync(0xffffffffu, sq, o);
    }
    __shared__ float ss[4], ssq[4];
    if ((tid & 31) == 0) { ss[tid >> 5] = s; ssq[tid >> 5] = sq; }
    __syncthreads();
    float ts = ss[0] + ss[1] + ss[2] + ss[3];
    float tq = ssq[0] + ssq[1] + ssq[2] + ssq[3];
    float mean = ts * (1.0f / CC);
    float var  = tq * (1.0f / CC) - mean * mean;
    float inv  = rsqrtf(var + EPSF);
    float4 g4 = ((const float4*)gamma)[tid];
    float4 b4 = ((const float4*)beta)[tid];
    __half2 p0{__float2half((v.x - mean) * inv * g4.x + b4.x),
               __float2half((v.y - mean) * inv * g4.y + b4.y)};
    __half2 p1{__float2half((v.z - mean) * inv * g4.z + b4.z),
               __float2half((v.w - mean) * inv * g4.w + b4.w)};
    uint2 pk;
    pk.x = *(uint32_t*)&p0;
    pk.y = *(uint32_t*)&p1;
    ((uint2*)(out + (size_t)token * CC))[tid] = pk;
}

// ---------------- zero scratch accumulators ---------------------------------
__global__ void zero_kernel()
{
    int i = blockIdx.x * blockDim.x + threadIdx.x;
    if (i < BB*HEADS*HD*HD) g_kv[i] = 0.f;
    if (i < BB*HEADS*HD)    g_ksum[i] = 0.f;
    if (i < NTOK)         { g_musum[i] = 0.f; g_sqsum[i] = 0.f; }
    if (i < CC)           { g_sum[i] = 0.f; g_sumsq[i] = 0.f; }
}

// ---------------- kv = k^T v per (b,h); ksum = sum_n k (fp16 in) -------------
__global__ __launch_bounds__(256)
void kv_kernel(const __half* __restrict__ qkv)
{
    int bh = blockIdx.x;
    int b = bh >> 3, h = bh & 7;
    const __half* kbase = qkv + (size_t)(b*NN)*1536 +  512 + h*64;
    const __half* vbase = qkv + (size_t)(b*NN)*1536 + 1024 + h*64;
    __shared__ float ks[64][64];
    __shared__ float vs[64][64];
    int tid = threadIdx.x;
    int lr  = tid >> 3;
    int lc8 = (tid & 7) * 8;
    int ty = tid >> 4, tx = tid & 15;
    float acc[4][4];
    #pragma unroll
    for (int i = 0; i < 4; i++)
        #pragma unroll
        for (int j = 0; j < 4; j++) acc[i][j] = 0.f;
    float ksum8[8];
    #pragma unroll
    for (int j = 0; j < 8; j++) ksum8[j] = 0.f;
    int n0 = blockIdx.y * 256;
    for (int s = 0; s < 4; s++) {
        int base = n0 + s * 64;
        #pragma unroll
        for (int p = 0; p < 2; p++) {
            int r = p * 32 + lr;
            uint4 kk = *(const uint4*)(kbase + (size_t)(base + r) * 1536 + lc8);
            uint4 vv = *(const uint4*)(vbase + (size_t)(base + r) * 1536 + lc8);
            const __half2* kh = (const __half2*)&kk;
            const __half2* vh = (const __half2*)&vv;
            #pragma unroll
            for (int j = 0; j < 4; j++){
                float2 kf = __half22float2(kh[j]);
                float2 vf = __half22float2(vh[j]);
                ks[r][lc8 + 2*j    ] = kf.x;
                ks[r][lc8 + 2*j + 1] = kf.y;
                vs[r][lc8 + 2*j    ] = vf.x;
                vs[r][lc8 + 2*j + 1] = vf.y;
                ksum8[2*j]     += kf.x;
                ksum8[2*j + 1] += kf.y;
            }
        }
        __syncthreads();
        #pragma unroll 8
        for (int n = 0; n < 64; n++) {
            float rk[4], rv[4];
            *(float4*)rk = *(const float4*)&ks[n][ty * 4];
            *(float4*)rv = *(const float4*)&vs[n][tx * 4];
            #pragma unroll
            for (int i = 0; i < 4; i++)
                #pragma unroll
                for (int j = 0; j < 4; j++)
                    acc[i][j] += rk[i] * rv[j];
        }
        __syncthreads();
    }
    float* kvout = g_kv + bh * 4096;
    #pragma unroll
    for (int i = 0; i < 4; i++)
        #pragma unroll
        for (int j = 0; j < 4; j++)
            atomicAdd(&kvout[(ty*4 + i) * 64 + tx*4 + j], acc[i][j]);
    #pragma unroll
    for (int j = 0; j < 8; j++){
        ksum8[j] += __shfl_xor_sync(0xffffffffu, ksum8[j], 8);
        ksum8[j] += __shfl_xor_sync(0xffffffffu, ksum8[j], 16);
    }
    if ((tid & 31) < 8){
        #pragma unroll
        for (int j = 0; j < 8; j++)
            atomicAdd(&g_ksum[bh * 64 + lc8 + j], ksum8[j]);
    }
}

// ---------------- attn: warp-autonomous, no inner-loop syncs -----------------
__global__ __launch_bounds__(256)
void attn_kernel(const __half* __restrict__ qkv, __half* __restrict__ attn)
{
    int bh = blockIdx.x;
    int b = bh >> 3, h = bh & 7;
    __shared__ float kvs[64][64];
    __shared__ float norms[64];
    int tid = threadIdx.x;
    for (int i = tid; i < 4096; i += 256)
        kvs[i >> 6][i & 63] = g_kv[bh * 4096 + i];
    if (tid < 64) norms[tid] = fmaxf(g_ksum[bh * 64 + tid], CLAMPF);
    __syncthreads();
    int wid = tid >> 5, lane = tid & 31;
    const __half* qbase = qkv + (size_t)(b*NN)*1536 + h*64;
    int nbase = blockIdx.y * 256 + wid * 32;
    for (int it = 0; it < 32; it++) {
        int n = nbase + it;
        __half2 q2 = *(const __half2*)(qbase + (size_t)n * 1536 + 2*lane);
        float2 qf = __half22float2(q2);
        float acc0 = 0.f, acc1 = 0.f, den = 0.f;
        #pragma unroll
        for (int d = 0; d < 64; d += 2){
            float qa = __shfl_sync(0xffffffffu, qf.x, d >> 1);
            float qb = __shfl_sync(0xffffffffu, qf.y, d >> 1);
            acc0 += qa * kvs[d][lane];
            acc1 += qa * kvs[d][lane + 32];
            den  += qa * norms[d];
            acc0 += qb * kvs[d+1][lane];
            acc1 += qb * kvs[d+1][lane + 32];
            den  += qb * norms[d+1];
        }
        float inv = 1.0f / fmaxf(den, CLAMPF);
        __half* orow = attn + (size_t)(b*NN + n) * CC + h*64;
        orow[lane]      = __float2half(acc0 * inv);
        orow[lane + 32] = __float2half(acc1 * inv);
    }
}

// ---------------- conv1: fused LN2-apply + dw7x7 + gelu + bn stats -----------
__global__ __launch_bounds__(256)
void conv1_kernel(const __half* __restrict__ ap, const float* __restrict__ cw,
                  const float* __restrict__ cb, const float* __restrict__ lg,
                  const float* __restrict__ lb)
{
    int b  = blockIdx.z;
    int c0 = blockIdx.y * 32;
    int h0 = (blockIdx.x >> 3) * 8;
    int w0 = (blockIdx.x & 7) * 8;
    __shared__ float ins[14][14][32];
    __shared__ float ws[32][49];
    __shared__ float sg[32], sb[32];
    __shared__ float rsum[8][32], rsq[8][32];
    int tid = threadIdx.x;
    if (tid < 32){ sg[tid] = lg[c0 + tid]; sb[tid] = lb[c0 + tid]; }
    for (int i = tid; i < 32 * 49; i += 256)
        ws[i / 49][i % 49] = cw[(c0 + i / 49) * 49 + (i % 49)];
    __syncthreads();
    for (int i = tid; i < 14 * 14 * 32; i += 256) {
        int ic = i & 31; int pos = i >> 5;
        int iw = pos % 14, ih = pos / 14;
        int gh = h0 + ih - 3, gw = w0 + iw - 3;
        float v = 0.f;
        if (gh >= 0 && gh < HH && gw >= 0 && gw < WW){
            size_t tok = (size_t)(b*NN) + gh*WW + gw;
            float a = __half2float(ap[tok * CC + c0 + ic]);
            v = (a - g_mu[tok]) * g_rinv[tok] * sg[ic] + sb[ic];
        }
        ins[ih][iw][ic] = v;
    }
    __syncthreads();
    int oc = tid & 31;
    int ow = tid >> 5;
    float wr[49];
    #pragma unroll
    for (int j = 0; j < 49; j++) wr[j] = ws[oc][j];
    float bias = cb[c0 + oc];
    float acc[8];
    #pragma unroll
    for (int oh = 0; oh < 8; oh++) acc[oh] = bias;
    #pragma unroll
    for (int ih = 0; ih < 14; ih++){
        float v[7];
        #pragma unroll
        for (int dw = 0; dw < 7; dw++) v[dw] = ins[ih][ow + dw][oc];
        #pragma unroll
        for (int oh = 0; oh < 8; oh++){
            int dh = ih - oh;
            if (dh >= 0 && dh < 7){
                #pragma unroll
                for (int dw = 0; dw < 7; dw++)
                    acc[oh] += v[dw] * wr[dh * 7 + dw];
            }
        }
    }
    float psum = 0.f, psq = 0.f;
    #pragma unroll
    for (int oh = 0; oh < 8; oh++){
        float yv = acc[oh] * normcdff(acc[oh]);
        g_y[((size_t)(b*NN) + (h0+oh)*WW + (w0+ow)) * CC + c0 + oc] = __float2half(yv);
        psum += yv; psq += yv * yv;
    }
    rsum[ow][oc] = psum; rsq[ow][oc] = psq;
    __syncthreads();
    if (tid < 32) {
        float s = 0.f, q = 0.f;
        #pragma unroll
        for (int i = 0; i < 8; i++) { s += rsum[i][tid]; q += rsq[i][tid]; }
        atomicAdd(&g_sum[c0 + tid], s);
        atomicAdd(&g_sumsq[c0 + tid], q);
    }
}

// ---------------- conv2: BN-apply + depthwise 7x7 + triple residual ----------
__global__ __launch_bounds__(256)
void conv2_kernel(const float* __restrict__ x, const float* __restrict__ cw,
                  const float* __restrict__ cb, const float* __restrict__ bng,
                  const float* __restrict__ bnb, float* __restrict__ out)
{
    int b  = blockIdx.z;
    int c0 = blockIdx.y * 32;
    int h0 = (blockIdx.x >> 3) * 8;
    int w0 = (blockIdx.x & 7) * 8;
    __shared__ float ins[14][14][32];
    __shared__ float ws[32][49];
    __shared__ float scs[32], shs[32];
    int tid = threadIdx.x;
    if (tid < 32) {
        int c = c0 + tid;
        float m   = g_sum[c]   * (1.0f / (float)NTOK);
        float var = g_sumsq[c] * (1.0f / (float)NTOK) - m * m;
        float inv = rsqrtf(var + EPSF);
        float sc = bng[c] * inv;
        scs[tid] = sc;
        shs[tid] = bnb[c] - m * sc;
    }
    for (int i = tid; i < 32 * 49; i += 256)
        ws[i / 49][i % 49] = cw[(c0 + i / 49) * 49 + (i % 49)];
    __syncthreads();
    for (int i = tid; i < 14 * 14 * 32; i += 256) {
        int ic = i & 31; int pos = i >> 5;
        int iw = pos % 14, ih = pos / 14;
        int gh = h0 + ih - 3, gw = w0 + iw - 3;
        float v = 0.f;
        if (gh >= 0 && gh < HH && gw >= 0 && gw < WW)
            v = __half2float(g_y[((size_t)(b*NN) + gh*WW + gw) * CC + c0 + ic])
                * scs[ic] + shs[ic];
        ins[ih][iw][ic] = v;
    }
    __syncthreads();
    int oc = tid & 31;
    int ow = tid >> 5;
    float wr[49];
    #pragma unroll
    for (int j = 0; j < 49; j++) wr[j] = ws[oc][j];
    float bias = cb[c0 + oc];
    float acc[8];
    #pragma unroll
    for (int oh = 0; oh < 8; oh++) acc[oh] = bias;
    #pragma unroll
    for (int ih = 0; ih < 14; ih++){
        float v[7];
        #pragma unroll
        for (int dw = 0; dw < 7; dw++) v[dw] = ins[ih][ow + dw][oc];
        #pragma unroll
        for (int oh = 0; oh < 8; oh++){
            int dh = ih - oh;
            if (dh >= 0 && dh < 7){
                #pragma unroll
                for (int dw = 0; dw < 7; dw++)
                    acc[oh] += v[dw] * wr[dh * 7 + dw];
            }
        }
    }
    #pragma unroll
    for (int oh = 0; oh < 8; oh++){
        size_t idx = ((size_t)(b*NN) + (h0+oh)*WW + (w0+ow)) * CC + c0 + oc;
        out[idx] = x[idx] + __half2float(g_attnproj[idx]) + acc[oh];
    }
}

// ---------------- launch ----------------------------------------------------
extern "C" void kernel_launch(void* const* d_in, const int* in_sizes, int n_in,
                              void* d_out, int out_size)
{
    const float* x      = (const float*)d_in[0];
    const float* qkv_w  = (const float*)d_in[1];
    const float* qkv_b  = (const float*)d_in[2];
    const float* out_w  = (const float*)d_in[3];
    const float* out_b  = (const float*)d_in[4];
    const float* pre_g  = (const float*)d_in[5];
    const float* pre_b  = (const float*)d_in[6];
    const float* lcm_g  = (const float*)d_in[7];
    const float* lcm_b  = (const float*)d_in[8];
    const float* ci_w   = (const float*)d_in[9];
    const float* ci_b   = (const float*)d_in[10];
    const float* bn_g   = (const float*)d_in[11];
    const float* bn_b   = (const float*)d_in[12];
    const float* co_w   = (const float*)d_in[13];
    const float* co_b   = (const float*)d_in[14];
    float* out = (float*)d_out;

    __half *p_normedh, *p_qkvh, *p_attnh, *p_attnproj, *p_wqkvTh, *p_woutTh;
    cudaGetSymbolAddress((void**)&p_normedh,  g_normedh);
    cudaGetSymbolAddress((void**)&p_qkvh,     g_qkvh);
    cudaGetSymbolAddress((void**)&p_attnh,    g_attnh);
    cudaGetSymbolAddress((void**)&p_attnproj, g_attnproj);
    cudaGetSymbolAddress((void**)&p_wqkvTh,   g_wqkvTh);
    cudaGetSymbolAddress((void**)&p_woutTh,   g_woutTh);

    cudaFuncSetAttribute(gemm_mma_kernel<__half, false>,
        cudaFuncAttributeMaxDynamicSharedMemorySize, GSMEM);
    cudaFuncSetAttribute(gemm_mma_kernel<__half, true>,
        cudaFuncAttributeMaxDynamicSharedMemorySize, GSMEM);

    // 1. merged weight transpose ([K,N] -> [N,K], fp16)
    transpose_kernel<<<dim3(64, 16), dim3(32,8)>>>(qkv_w, out_w, p_wqkvTh, p_woutTh);
    // 2. zero accumulators
    zero_kernel<<<(BB*HEADS*HD*HD + 255) / 256, 256>>>();
    // 3. pre-layernorm -> fp16
    ln_kernel<<<NTOK, 128>>>(x, pre_g, pre_b, p_normedh);
    // 4. qkv gemm (3-stage pipeline) + relu on cols [0,1024)
    gemm_mma_kernel<__half, false><<<dim3(1536/128, NTOK/128), 256, GSMEM>>>(
        p_normedh, p_wqkvTh, qkv_b, p_qkvh, 1536, 1024);
    // 5. kv outer-product + ksum
    kv_kernel<<<dim3(BB*HEADS, 16), 256>>>(p_qkvh);
    // 6. attention apply -> fp16 (warp-autonomous)
    attn_kernel<<<dim3(BB*HEADS, 16), 256>>>(p_qkvh, p_attnh);
    // 7. output projection + fused LN2 row sums
    gemm_mma_kernel<__half, true><<<dim3(CC/128, NTOK/128), 256, GSMEM>>>(
        p_attnh, p_woutTh, out_b, p_attnproj, 512, 0);
    // 8. LN2 finalize (sums -> mu, rinv)
    ln_fin_kernel<<<NTOK/256, 256>>>();
    // 9. conv1 (LN2-apply fused) + gelu + bn stats -> fp16 y
    conv1_kernel<<<dim3(64, CC/32, BB), 256>>>(p_attnproj, ci_w, ci_b, lcm_g, lcm_b);
    // 10. bn apply + conv2 + triple residual -> out
    conv2_kernel<<<dim3(64, CC/32, BB), 256>>>(x, co_w, co_b, bn_g, bn_b, out);
}

// round 15
// speedup vs baseline: 1.4073x; 1.2040x over previous
#include <cuda_runtime.h>
#include <cuda_fp16.h>
#include <math.h>
#include <cstdint>

#define BB    8
#define NN    4096
#define CC    512
#define NTOK  (BB*NN)        // 32768 tokens
#define HEADS 8
#define HD    64
#define HH    64
#define WW    64
#define EPSF  1e-5f
#define CLAMPF 100.0f

// ---------------- scratch (static device globals; no runtime alloc) ----------
__device__ __half g_normedh[NTOK*CC];              // 32 MB (GEMM1 A)
__device__ __half g_qkvh[(size_t)NTOK*3*CC];       // 96 MB (GEMM1 out, fp16)
__device__ __half g_attnh[NTOK*CC];                // 32 MB (GEMM2 A)
__device__ __half g_attnproj[NTOK*CC];             // 32 MB (GEMM2 out, fp16)
__device__ __half g_y[NTOK*CC];                    // 32 MB (conv1 out, fp16)
__device__ float g_mu[NTOK];                       // LN2 per-token mean
__device__ float g_rinv[NTOK];                     // LN2 per-token 1/std
__device__ float g_musum[NTOK];                    // LN2 partial row sums
__device__ float g_sqsum[NTOK];
__device__ float g_kv[BB*HEADS*HD*HD];
__device__ float g_ksum[BB*HEADS*HD];
__device__ __half g_kvbh[BB*HEADS*80*64];          // fp16 [n(v)|norms|pad][d] per bh
__device__ float g_sum[CC];
__device__ float g_sumsq[CC];
__device__ __half g_wqkvTh[3*CC*CC];               // [1536,512] fp16 transposed
__device__ __half g_woutTh[CC*CC];                 // [512,512]  fp16 transposed

// ============================ PTX helpers ====================================
__device__ __forceinline__ uint32_t smem_u32(const void* p){
    uint32_t a;
    asm("{ .reg .u64 t; cvta.to.shared.u64 t, %1; cvt.u32.u64 %0, t; }"
        : "=r"(a) : "l"(p));
    return a;
}
__device__ __forceinline__ void cpa16(uint32_t dst, const void* src){
    asm volatile("cp.async.ca.shared.global [%0], [%1], 16;"
                 :: "r"(dst), "l"(src) : "memory");
}
__device__ __forceinline__ void cpa_commit(){
    asm volatile("cp.async.commit_group;" ::: "memory");
}
template<int N> __device__ __forceinline__ void cpa_wait(){
    asm volatile("cp.async.wait_group %0;" :: "n"(N) : "memory");
}
__device__ __forceinline__ void mma_f16(float* d, const uint32_t* a, const uint32_t* b){
    asm volatile("mma.sync.aligned.m16n8k16.row.col.f32.f16.f16.f32 "
        "{%0,%1,%2,%3}, {%4,%5,%6,%7}, {%8,%9}, {%0,%1,%2,%3};"
        : "+f"(d[0]), "+f"(d[1]), "+f"(d[2]), "+f"(d[3])
        : "r"(a[0]), "r"(a[1]), "r"(a[2]), "r"(a[3]), "r"(b[0]), "r"(b[1]));
}
__device__ __forceinline__ void ldsm4(uint32_t& r0, uint32_t& r1,
                                      uint32_t& r2, uint32_t& r3, uint32_t addr){
    asm volatile("ldmatrix.sync.aligned.m8n8.x4.shared.b16 {%0,%1,%2,%3}, [%4];"
        : "=r"(r0), "=r"(r1), "=r"(r2), "=r"(r3) : "r"(addr));
}

// ============================ mma.sync fp16 GEMM =============================
// D[M,Nn] = A[M,512] @ Bt[Nn,512]^T + bias, relu on cols < nrelu.
// CTA 128x128, 8 warps (4m x 2n), warp tile 32x64. BK=32, ldmatrix,
// 4-stage cp.async pipeline, one __syncthreads per K-tile, 2 CTA/SM.
#define GK    512
#define GBK   32
#define KPADH 40              // halves per row (80B stride; conflict-free LDSM)
#define NKT   (GK/GBK)        // 16 k-tiles
#define ROWB  (KPADH*2)       // 80 bytes per smem row
#define ASTG  (128*ROWB)      // 10240 bytes per stage per operand
#define NSTG  4
#define GSMEM (2*NSTG*ASTG)   // 81920 bytes total (4 stages x A,B)

template<typename OUT, bool STATS>
__global__ void __launch_bounds__(256, 2)
gemm_mma_kernel(const __half* __restrict__ A,
                const __half* __restrict__ Bt,
                const float* __restrict__ bias, OUT* __restrict__ Cout,
                int Nn, int nrelu)
{
    extern __shared__ __half dsm[];
    __shared__ float ssum[128], ssq[128];
    uint32_t base = smem_u32(dsm);
    const uint32_t BOFF = NSTG * ASTG;
    int tid = threadIdx.x;
    int wid = tid >> 5, lane = tid & 31;
    int gid = lane >> 2, tig = lane & 3;
    int warpM = (wid >> 1) * 32;
    int warpN = (wid & 1) * 64;
    int row0 = blockIdx.y * 128, col0 = blockIdx.x * 128;
    const __half* Ab = A  + (size_t)row0 * GK;
    const __half* Bb = Bt + (size_t)col0 * GK;

    if (STATS && tid < 128){ ssum[tid] = 0.f; ssq[tid] = 0.f; }

    int r0i = tid >> 2,          c0i = tid & 3;
    int r1i = (tid + 256) >> 2,  c1i = c0i;
    uint32_t aoff0 = (uint32_t)(r0i * ROWB + c0i * 16);
    uint32_t aoff1 = (uint32_t)(r1i * ROWB + c1i * 16);

    int aRow = warpM + (lane & 15);
    int aCol = (lane >> 4) * 8;
    int bRow = warpN + (lane >> 4) * 8 + (lane & 7);
    int bCol = ((lane >> 3) & 1) * 8;
    uint32_t aBase = (uint32_t)(aRow * ROWB + aCol * 2);
    uint32_t bBase = (uint32_t)(bRow * ROWB + bCol * 2);

    float acc[2][8][4];
    #pragma unroll
    for (int mi = 0; mi < 2; mi++)
        #pragma unroll
        for (int ni = 0; ni < 8; ni++)
            #pragma unroll
            for (int r = 0; r < 4; r++) acc[mi][ni][r] = 0.f;

    auto load_tile = [&](int t, int s){
        int k0 = t * GBK;
        uint32_t sa = base + s * ASTG;
        uint32_t sb = base + BOFF + s * ASTG;
        cpa16(sa + aoff0, Ab + (size_t)r0i * GK + k0 + c0i * 8);
        cpa16(sa + aoff1, Ab + (size_t)r1i * GK + k0 + c1i * 8);
        cpa16(sb + aoff0, Bb + (size_t)r0i * GK + k0 + c0i * 8);
        cpa16(sb + aoff1, Bb + (size_t)r1i * GK + k0 + c1i * 8);
    };

    load_tile(0, 0); cpa_commit();
    load_tile(1, 1); cpa_commit();
    load_tile(2, 2); cpa_commit();

    for (int t = 0; t < NKT; t++){
        int s = t % NSTG;
        cpa_wait<2>();
        __syncthreads();
        if (t + 3 < NKT) load_tile(t + 3, (t + 3) % NSTG);
        cpa_commit();
        uint32_t sa = base + s * ASTG;
        uint32_t sb = base + BOFF + s * ASTG;
        #pragma unroll
        for (int ks = 0; ks < 2; ks++){
            int k0 = ks * 16;
            uint32_t a[2][4], bfr[8][2];
            #pragma unroll
            for (int mi = 0; mi < 2; mi++){
                uint32_t ad = sa + aBase + (uint32_t)(mi * 16 * ROWB + k0 * 2);
                ldsm4(a[mi][0], a[mi][1], a[mi][2], a[mi][3], ad);
            }
            #pragma unroll
            for (int p = 0; p < 4; p++){
                uint32_t bd = sb + bBase + (uint32_t)(p * 16 * ROWB + k0 * 2);
                ldsm4(bfr[2*p][0], bfr[2*p][1], bfr[2*p+1][0], bfr[2*p+1][1], bd);
            }
            #pragma unroll
            for (int mi = 0; mi < 2; mi++)
                #pragma unroll
                for (int ni = 0; ni < 8; ni++)
                    mma_f16(acc[mi][ni], a[mi], bfr[ni]);
        }
    }

    // epilogue: bias + optional relu (+ fused row stats)
    #pragma unroll
    for (int mi = 0; mi < 2; mi++){
        #pragma unroll
        for (int rr = 0; rr < 2; rr++){
            int rloc = warpM + mi * 16 + rr * 8 + gid;
            int r = row0 + rloc;
            float s = 0.f, sq = 0.f;
            #pragma unroll
            for (int ni = 0; ni < 8; ni++){
                int c = col0 + warpN + ni * 8 + tig * 2;
                float ox = acc[mi][ni][rr * 2 + 0] + bias[c + 0];
                float oy = acc[mi][ni][rr * 2 + 1] + bias[c + 1];
                if (c < nrelu){
                    ox = fmaxf(ox, 0.f);
                    oy = fmaxf(oy, 0.f);
                }
                if (STATS){
                    s  += ox + oy;
                    sq += ox * ox + oy * oy;
                }
                if constexpr (sizeof(OUT) == 4) {
                    float2 o{ox, oy};
                    *(float2*)((float*)Cout + (size_t)r * Nn + c) = o;
                } else {
                    __half2 o{__float2half(ox), __float2half(oy)};
                    *(__half2*)((__half*)Cout + (size_t)r * Nn + c) = o;
                }
            }
            if (STATS){
                s  += __shfl_xor_sync(0xffffffffu, s, 1);
                s  += __shfl_xor_sync(0xffffffffu, s, 2);
                sq += __shfl_xor_sync(0xffffffffu, sq, 1);
                sq += __shfl_xor_sync(0xffffffffu, sq, 2);
                if (tig == 0){
                    atomicAdd(&ssum[rloc], s);
                    atomicAdd(&ssq[rloc], sq);
                }
            }
        }
    }
    if (STATS){
        __syncthreads();
        if (tid < 128){
            atomicAdd(&g_musum[row0 + tid], ssum[tid]);
            atomicAdd(&g_sqsum[row0 + tid], ssq[tid]);
        }
    }
}

// ---------------- LN2 finalize: sums -> mu, rinv -----------------------------
__global__ void ln_fin_kernel()
{
    int i = blockIdx.x * blockDim.x + threadIdx.x;
    float mean = g_musum[i] * (1.0f / CC);
    float var  = g_sqsum[i] * (1.0f / CC) - mean * mean;
    g_mu[i]   = mean;
    g_rinv[i] = rsqrtf(var + EPSF);
}

// ---------------- merged weight transpose -> fp16 ----------------------------
__global__ void transpose_kernel(const float* __restrict__ qkvw,
                                 const float* __restrict__ outw,
                                 __half* __restrict__ qkvT,
                                 __half* __restrict__ outT)
{
    __shared__ float tile[32][33];
    const float* in; __half* outp; int Cc, bxi;
    if (blockIdx.x < 48){ in = qkvw; outp = qkvT; Cc = 1536; bxi = blockIdx.x; }
    else                { in = outw; outp = outT; Cc = 512;  bxi = blockIdx.x - 48; }
    int bx = bxi * 32, by = blockIdx.y * 32;
    int tx = threadIdx.x, ty = threadIdx.y;   // 32 x 8
    #pragma unroll
    for (int i = 0; i < 32; i += 8)
        tile[ty + i][tx] = in[(size_t)(by + ty + i) * Cc + bx + tx];
    __syncthreads();
    #pragma unroll
    for (int i = 0; i < 32; i += 8)
        outp[(size_t)(bx + ty + i) * 512 + by + tx] = __float2half(tile[tx][ty + i]);
}

// ---------------- layernorm over C=512 -> fp16 -------------------------------
__global__ void ln_kernel(const float* __restrict__ in,
                          const float* __restrict__ gamma,
                          const float* __restrict__ beta,
                          __half* __restrict__ out)
{
    int token = blockIdx.x;
    const float4* row = (const float4*)(in + (size_t)token * CC);
    int tid = threadIdx.x;
    float4 v = row[tid];
    float s  = v.x + v.y + v.z + v.w;
    float sq = v.x*v.x + v.y*v.y + v.z*v.z + v.w*v.w;
    #pragma unroll
    for (int o = 16; o; o >>= 1) {
        s  += __shfl_xor_sync(0xffffffffu, s,  o);
        sq += __shfl_xor_sync(0xffffffffu, sq, o);
    }
    __shared__ float ss[4], ssq[4];
    if ((tid & 31) == 0) { ss[tid >> 5] = s; ssq[tid >> 5] = sq; }
    __syncthreads();
    float ts = ss[0] + ss[1] + ss[2] + ss[3];
    float tq = ssq[0] + ssq[1] + ssq[2] + ssq[3];
    float mean = ts * (1.0f / CC);
    float var  = tq * (1.0f / CC) - mean * mean;
    float inv  = rsqrtf(var + EPSF);
    float4 g4 = ((const float4*)gamma)[tid];
    float4 b4 = ((const float4*)beta)[tid];
    __half2 p0{__float2half((v.x - mean) * inv * g4.x + b4.x),
               __float2half((v.y - mean) * inv * g4.y + b4.y)};
    __half2 p1{__float2half((v.z - mean) * inv * g4.z + b4.z),
               __float2half((v.w - mean) * inv * g4.w + b4.w)};
    uint2 pk;
    pk.x = *(uint32_t*)&p0;
    pk.y = *(uint32_t*)&p1;
    ((uint2*)(out + (size_t)token * CC))[tid] = pk;
}

// ---------------- zero scratch accumulators ---------------------------------
__global__ void zero_kernel()
{
    int i = blockIdx.x * blockDim.x + threadIdx.x;
    if (i < BB*HEADS*HD*HD) g_kv[i] = 0.f;
    if (i < BB*HEADS*HD)    g_ksum[i] = 0.f;
    if (i < NTOK)         { g_musum[i] = 0.f; g_sqsum[i] = 0.f; }
    if (i < CC)           { g_sum[i] = 0.f; g_sumsq[i] = 0.f; }
}

// ---------------- kv = k^T v per (b,h); ksum = sum_n k (fp16 in) -------------
__global__ __launch_bounds__(256)
void kv_kernel(const __half* __restrict__ qkv)
{
    int bh = blockIdx.x;
    int b = bh >> 3, h = bh & 7;
    const __half* kbase = qkv + (size_t)(b*NN)*1536 +  512 + h*64;
    const __half* vbase = qkv + (size_t)(b*NN)*1536 + 1024 + h*64;
    __shared__ float ks[64][64];
    __shared__ float vs[64][64];
    int tid = threadIdx.x;
    int lr  = tid >> 3;
    int lc8 = (tid & 7) * 8;
    int ty = tid >> 4, tx = tid & 15;
    float acc[4][4];
    #pragma unroll
    for (int i = 0; i < 4; i++)
        #pragma unroll
        for (int j = 0; j < 4; j++) acc[i][j] = 0.f;
    float ksum8[8];
    #pragma unroll
    for (int j = 0; j < 8; j++) ksum8[j] = 0.f;
    int n0 = blockIdx.y * 256;
    for (int s = 0; s < 4; s++) {
        int base = n0 + s * 64;
        #pragma unroll
        for (int p = 0; p < 2; p++) {
            int r = p * 32 + lr;
            uint4 kk = *(const uint4*)(kbase + (size_t)(base + r) * 1536 + lc8);
            uint4 vv = *(const uint4*)(vbase + (size_t)(base + r) * 1536 + lc8);
            const __half2* kh = (const __half2*)&kk;
            const __half2* vh = (const __half2*)&vv;
            #pragma unroll
            for (int j = 0; j < 4; j++){
                float2 kf = __half22float2(kh[j]);
                float2 vf = __half22float2(vh[j]);
                ks[r][lc8 + 2*j    ] = kf.x;
                ks[r][lc8 + 2*j + 1] = kf.y;
                vs[r][lc8 + 2*j    ] = vf.x;
                vs[r][lc8 + 2*j + 1] = vf.y;
                ksum8[2*j]     += kf.x;
                ksum8[2*j + 1] += kf.y;
            }
        }
        __syncthreads();
        #pragma unroll 8
        for (int n = 0; n < 64; n++) {
            float rk[4], rv[4];
            *(float4*)rk = *(const float4*)&ks[n][ty * 4];
            *(float4*)rv = *(const float4*)&vs[n][tx * 4];
            #pragma unroll
            for (int i = 0; i < 4; i++)
                #pragma unroll
                for (int j = 0; j < 4; j++)
                    acc[i][j] += rk[i] * rv[j];
        }
        __syncthreads();
    }
    float* kvout = g_kv + bh * 4096;
    #pragma unroll
    for (int i = 0; i < 4; i++)
        #pragma unroll
        for (int j = 0; j < 4; j++)
            atomicAdd(&kvout[(ty*4 + i) * 64 + tx*4 + j], acc[i][j]);
    #pragma unroll
    for (int j = 0; j < 8; j++){
        ksum8[j] += __shfl_xor_sync(0xffffffffu, ksum8[j], 8);
        ksum8[j] += __shfl_xor_sync(0xffffffffu, ksum8[j], 16);
    }
    if ((tid & 31) < 8){
        #pragma unroll
        for (int j = 0; j < 8; j++)
            atomicAdd(&g_ksum[bh * 64 + lc8 + j], ksum8[j]);
    }
}

// ---------------- kvfin: build fp16 B matrix [80][64] per bh -----------------
// B[n][d] = kv[d][n] for n<64; B[64][d] = max(ksum[d],100); rows 65-79 = 0.
__global__ void kvfin_kernel()
{
    int bh = blockIdx.x;
    int tid = threadIdx.x;
    for (int i = tid; i < 80*64; i += 256){
        int n = i >> 6, d = i & 63;
        float v;
        if (n < 64)      v = g_kv[bh * 4096 + d * 64 + n];
        else if (n == 64) v = fmaxf(g_ksum[bh * 64 + d], CLAMPF);
        else             v = 0.f;
        g_kvbh[bh * 5120 + i] = __float2half(v);
    }
}

// ---------------- attn via mma: D = q @ [kv | norms]^T, divide, -> fp16 ------
// grid (64 bh, 32 token-tiles of 128), 256 threads = 8 warps x 16 tokens.
#define APAD 72   // halves per smem row (144B stride: +4 banks/row, conflict-free)
__global__ __launch_bounds__(256)
void attn_kernel(const __half* __restrict__ qkv, __half* __restrict__ attn)
{
    __shared__ __half qs[128][APAD];
    __shared__ __half bs[80][APAD];
    int bh = blockIdx.x;
    int b = bh >> 3, h = bh & 7;
    int tok0 = blockIdx.y * 128;
    int tid = threadIdx.x;
    int wid = tid >> 5, lane = tid & 31;
    int gid = lane >> 2, tig = lane & 3;
    const __half* qbase = qkv + (size_t)(b*NN + tok0) * 1536 + h*64;
    const __half* kvb = g_kvbh + bh * 5120;

    uint32_t qsb = smem_u32(&qs[0][0]);
    uint32_t bsb = smem_u32(&bs[0][0]);
    // load q tile: 128 rows x 64 halves = 1024 x 16B chunks
    #pragma unroll
    for (int i = 0; i < 4; i++){
        int idx = tid + i * 256;
        int row = idx >> 3, c = (idx & 7) * 8;
        cpa16(qsb + (uint32_t)(row * APAD + c) * 2, qbase + (size_t)row * 1536 + c);
    }
    // load B: 80 rows x 64 halves = 640 x 16B chunks
    #pragma unroll
    for (int i = 0; i < 3; i++){
        int idx = tid + i * 256;
        if (idx < 640){
            int row = idx >> 3, c = (idx & 7) * 8;
            cpa16(bsb + (uint32_t)(row * APAD + c) * 2, kvb + row * 64 + c);
        }
    }
    cpa_commit();
    cpa_wait<0>();
    __syncthreads();

    int aRow = wid * 16 + (lane & 15);
    int aCol = (lane >> 4) * 8;
    int bRow = (lane >> 4) * 8 + (lane & 7);
    int bCol = ((lane >> 3) & 1) * 8;
    uint32_t aBase = qsb + (uint32_t)(aRow * APAD + aCol) * 2;
    uint32_t bBase = bsb + (uint32_t)(bRow * APAD + bCol) * 2;

    float acc[10][4];
    #pragma unroll
    for (int ni = 0; ni < 10; ni++)
        #pragma unroll
        for (int r = 0; r < 4; r++) acc[ni][r] = 0.f;

    #pragma unroll
    for (int ks = 0; ks < 4; ks++){
        int k0 = ks * 16;
        uint32_t a[4], bf[10][2];
        ldsm4(a[0], a[1], a[2], a[3], aBase + (uint32_t)(k0 * 2));
        #pragma unroll
        for (int p = 0; p < 5; p++){
            uint32_t bd = bBase + (uint32_t)(p * 16 * APAD + k0) * 2;
            ldsm4(bf[2*p][0], bf[2*p][1], bf[2*p+1][0], bf[2*p+1][1], bd);
        }
        #pragma unroll
        for (int ni = 0; ni < 9; ni++)
            mma_f16(acc[ni], a, bf[ni]);
    }

    // denom: column 64 lives in frag ni=8, tig=0 (c0 for row gid, c2 for gid+8)
    float d0 = __shfl_sync(0xffffffffu, acc[8][0], lane & 0x1C);
    float d8 = __shfl_sync(0xffffffffu, acc[8][2], lane & 0x1C);
    float i0 = 1.0f / fmaxf(d0, CLAMPF);
    float i8 = 1.0f / fmaxf(d8, CLAMPF);

    __half* obase = attn + (size_t)(b*NN + tok0 + wid*16) * CC + h*64;
    #pragma unroll
    for (int ni = 0; ni < 8; ni++){
        int c = ni * 8 + tig * 2;
        __half2 o0{__float2half(acc[ni][0] * i0), __float2half(acc[ni][1] * i0)};
        __half2 o8{__float2half(acc[ni][2] * i8), __float2half(acc[ni][3] * i8)};
        *(__half2*)(obase + (size_t)gid * CC + c) = o0;
        *(__half2*)(obase + (size_t)(gid + 8) * CC + c) = o8;
    }
}

// ---------------- conv1: fused LN2-apply + dw7x7 + gelu + bn stats -----------
__global__ __launch_bounds__(256)
void conv1_kernel(const __half* __restrict__ ap, const float* __restrict__ cw,
                  const float* __restrict__ cb, const float* __restrict__ lg,
                  const float* __restrict__ lb)
{
    int b  = blockIdx.z;
    int c0 = blockIdx.y * 32;
    int h0 = (blockIdx.x >> 3) * 8;
    int w0 = (blockIdx.x & 7) * 8;
    __shared__ float ins[14][14][32];
    __shared__ float ws[32][49];
    __shared__ float sg[32], sb[32];
    __shared__ float rsum[8][32], rsq[8][32];
    int tid = threadIdx.x;
    if (tid < 32){ sg[tid] = lg[c0 + tid]; sb[tid] = lb[c0 + tid]; }
    for (int i = tid; i < 32 * 49; i += 256)
        ws[i / 49][i % 49] = cw[(c0 + i / 49) * 49 + (i % 49)];
    __syncthreads();
    for (int i = tid; i < 14 * 14 * 32; i += 256) {
        int ic = i & 31; int pos = i >> 5;
        int iw = pos % 14, ih = pos / 14;
        int gh = h0 + ih - 3, gw = w0 + iw - 3;
        float v = 0.f;
        if (gh >= 0 && gh < HH && gw >= 0 && gw < WW){
            size_t tok = (size_t)(b*NN) + gh*WW + gw;
            float a = __half2float(ap[tok * CC + c0 + ic]);
            v = (a - g_mu[tok]) * g_rinv[tok] * sg[ic] + sb[ic];
        }
        ins[ih][iw][ic] = v;
    }
    __syncthreads();
    int oc = tid & 31;
    int ow = tid >> 5;
    float wr[49];
    #pragma unroll
    for (int j = 0; j < 49; j++) wr[j] = ws[oc][j];
    float bias = cb[c0 + oc];
    float acc[8];
    #pragma unroll
    for (int oh = 0; oh < 8; oh++) acc[oh] = bias;
    #pragma unroll
    for (int ih = 0; ih < 14; ih++){
        float v[7];
        #pragma unroll
        for (int dw = 0; dw < 7; dw++) v[dw] = ins[ih][ow + dw][oc];
        #pragma unroll
        for (int oh = 0; oh < 8; oh++){
            int dh = ih - oh;
            if (dh >= 0 && dh < 7){
                #pragma unroll
                for (int dw = 0; dw < 7; dw++)
                    acc[oh] += v[dw] * wr[dh * 7 + dw];
            }
        }
    }
    float psum = 0.f, psq = 0.f;
    #pragma unroll
    for (int oh = 0; oh < 8; oh++){
        float yv = acc[oh] * normcdff(acc[oh]);
        g_y[((size_t)(b*NN) + (h0+oh)*WW + (w0+ow)) * CC + c0 + oc] = __float2half(yv);
        psum += yv; psq += yv * yv;
    }
    rsum[ow][oc] = psum; rsq[ow][oc] = psq;
    __syncthreads();
    if (tid < 32) {
        float s = 0.f, q = 0.f;
        #pragma unroll
        for (int i = 0; i < 8; i++) { s += rsum[i][tid]; q += rsq[i][tid]; }
        atomicAdd(&g_sum[c0 + tid], s);
        atomicAdd(&g_sumsq[c0 + tid], q);
    }
}

// ---------------- conv2: BN-apply + depthwise 7x7 + triple residual ----------
__global__ __launch_bounds__(256)
void conv2_kernel(const float* __restrict__ x, const float* __restrict__ cw,
                  const float* __restrict__ cb, const float* __restrict__ bng,
                  const float* __restrict__ bnb, float* __restrict__ out)
{
    int b  = blockIdx.z;
    int c0 = blockIdx.y * 32;
    int h0 = (blockIdx.x >> 3) * 8;
    int w0 = (blockIdx.x & 7) * 8;
    __shared__ float ins[14][14][32];
    __shared__ float ws[32][49];
    __shared__ float scs[32], shs[32];
    int tid = threadIdx.x;
    if (tid < 32) {
        int c = c0 + tid;
        float m   = g_sum[c]   * (1.0f / (float)NTOK);
        float var = g_sumsq[c] * (1.0f / (float)NTOK) - m * m;
        float inv = rsqrtf(var + EPSF);
        float sc = bng[c] * inv;
        scs[tid] = sc;
        shs[tid] = bnb[c] - m * sc;
    }
    for (int i = tid; i < 32 * 49; i += 256)
        ws[i / 49][i % 49] = cw[(c0 + i / 49) * 49 + (i % 49)];
    __syncthreads();
    for (int i = tid; i < 14 * 14 * 32; i += 256) {
        int ic = i & 31; int pos = i >> 5;
        int iw = pos % 14, ih = pos / 14;
        int gh = h0 + ih - 3, gw = w0 + iw - 3;
        float v = 0.f;
        if (gh >= 0 && gh < HH && gw >= 0 && gw < WW)
            v = __half2float(g_y[((size_t)(b*NN) + gh*WW + gw) * CC + c0 + ic])
                * scs[ic] + shs[ic];
        ins[ih][iw][ic] = v;
    }
    __syncthreads();
    int oc = tid & 31;
    int ow = tid >> 5;
    float wr[49];
    #pragma unroll
    for (int j = 0; j < 49; j++) wr[j] = ws[oc][j];
    float bias = cb[c0 + oc];
    float acc[8];
    #pragma unroll
    for (int oh = 0; oh < 8; oh++) acc[oh] = bias;
    #pragma unroll
    for (int ih = 0; ih < 14; ih++){
        float v[7];
        #pragma unroll
        for (int dw = 0; dw < 7; dw++) v[dw] = ins[ih][ow + dw][oc];
        #pragma unroll
        for (int oh = 0; oh < 8; oh++){
            int dh = ih - oh;
            if (dh >= 0 && dh < 7){
                #pragma unroll
                for (int dw = 0; dw < 7; dw++)
                    acc[oh] += v[dw] * wr[dh * 7 + dw];
            }
        }
    }
    #pragma unroll
    for (int oh = 0; oh < 8; oh++){
        size_t idx = ((size_t)(b*NN) + (h0+oh)*WW + (w0+ow)) * CC + c0 + oc;
        out[idx] = x[idx] + __half2float(g_attnproj[idx]) + acc[oh];
    }
}

// ---------------- launch ----------------------------------------------------
extern "C" void kernel_launch(void* const* d_in, const int* in_sizes, int n_in,
                              void* d_out, int out_size)
{
    const float* x      = (const float*)d_in[0];
    const float* qkv_w  = (const float*)d_in[1];
    const float* qkv_b  = (const float*)d_in[2];
    const float* out_w  = (const float*)d_in[3];
    const float* out_b  = (const float*)d_in[4];
    const float* pre_g  = (const float*)d_in[5];
    const float* pre_b  = (const float*)d_in[6];
    const float* lcm_g  = (const float*)d_in[7];
    const float* lcm_b  = (const float*)d_in[8];
    const float* ci_w   = (const float*)d_in[9];
    const float* ci_b   = (const float*)d_in[10];
    const float* bn_g   = (const float*)d_in[11];
    const float* bn_b   = (const float*)d_in[12];
    const float* co_w   = (const float*)d_in[13];
    const float* co_b   = (const float*)d_in[14];
    float* out = (float*)d_out;

    __half *p_normedh, *p_qkvh, *p_attnh, *p_attnproj, *p_wqkvTh, *p_woutTh;
    cudaGetSymbolAddress((void**)&p_normedh,  g_normedh);
    cudaGetSymbolAddress((void**)&p_qkvh,     g_qkvh);
    cudaGetSymbolAddress((void**)&p_attnh,    g_attnh);
    cudaGetSymbolAddress((void**)&p_attnproj, g_attnproj);
    cudaGetSymbolAddress((void**)&p_wqkvTh,   g_wqkvTh);
    cudaGetSymbolAddress((void**)&p_woutTh,   g_woutTh);

    cudaFuncSetAttribute(gemm_mma_kernel<__half, false>,
        cudaFuncAttributeMaxDynamicSharedMemorySize, GSMEM);
    cudaFuncSetAttribute(gemm_mma_kernel<__half, true>,
        cudaFuncAttributeMaxDynamicSharedMemorySize, GSMEM);

    // 1. merged weight transpose ([K,N] -> [N,K], fp16)
    transpose_kernel<<<dim3(64, 16), dim3(32,8)>>>(qkv_w, out_w, p_wqkvTh, p_woutTh);
    // 2. zero accumulators
    zero_kernel<<<(BB*HEADS*HD*HD + 255) / 256, 256>>>();
    // 3. pre-layernorm -> fp16
    ln_kernel<<<NTOK, 128>>>(x, pre_g, pre_b, p_normedh);
    // 4. qkv gemm (4-stage pipeline) + relu on cols [0,1024)
    gemm_mma_kernel<__half, false><<<dim3(1536/128, NTOK/128), 256, GSMEM>>>(
        p_normedh, p_wqkvTh, qkv_b, p_qkvh, 1536, 1024);
    // 5. kv outer-product + ksum
    kv_kernel<<<dim3(BB*HEADS, 16), 256>>>(p_qkvh);
    // 6. build fp16 [kv | norms] B matrices
    kvfin_kernel<<<BB*HEADS, 256>>>();
    // 7. attention apply via mma -> fp16
    attn_kernel<<<dim3(BB*HEADS, 32), 256>>>(p_qkvh, p_attnh);
    // 8. output projection + fused LN2 row sums
    gemm_mma_kernel<__half, true><<<dim3(CC/128, NTOK/128), 256, GSMEM>>>(
        p_attnh, p_woutTh, out_b, p_attnproj, 512, 0);
    // 9. LN2 finalize (sums -> mu, rinv)
    ln_fin_kernel<<<NTOK/256, 256>>>();
    // 10. conv1 (LN2-apply fused) + gelu + bn stats -> fp16 y
    conv1_kernel<<<dim3(64, CC/32, BB), 256>>>(p_attnproj, ci_w, ci_b, lcm_g, lcm_b);
    // 11. bn apply + conv2 + triple residual -> out
    conv2_kernel<<<dim3(64, CC/32, BB), 256>>>(x, co_w, co_b, bn_g, bn_b, out);
}

// round 16
// speedup vs baseline: 1.7129x; 1.2172x over previous
#include <cuda_runtime.h>
#include <cuda_fp16.h>
#include <math.h>
#include <cstdint>

#define BB    8
#define NN    4096
#define CC    512
#define NTOK  (BB*NN)        // 32768 tokens
#define HEADS 8
#define HD    64
#define HH    64
#define WW    64
#define EPSF  1e-5f
#define CLAMPF 100.0f

// ---------------- scratch (static device globals; no runtime alloc) ----------
__device__ __half g_normedh[NTOK*CC];              // 32 MB (GEMM1 A)
__device__ __half g_qkvh[(size_t)NTOK*3*CC];       // 96 MB (GEMM1 out, fp16)
__device__ __half g_attnh[NTOK*CC];                // 32 MB (GEMM2 A)
__device__ __half g_attnproj[NTOK*CC];             // 32 MB (GEMM2 out, fp16)
__device__ __half g_y[NTOK*CC];                    // 32 MB (conv1 out, fp16)
__device__ float g_mu[NTOK];                       // LN2 per-token mean
__device__ float g_rinv[NTOK];                     // LN2 per-token 1/std
__device__ float g_musum[NTOK];                    // LN2 partial row sums
__device__ float g_sqsum[NTOK];
__device__ float g_kv[BB*HEADS*HD*HD];
__device__ float g_ksum[BB*HEADS*HD];
__device__ __half g_kvbh[BB*HEADS*80*64];          // fp16 [n(v)|norms|pad][d] per bh
__device__ float g_sum[CC];
__device__ float g_sumsq[CC];
__device__ __half g_wqkvTh[3*CC*CC];               // [1536,512] fp16 transposed
__device__ __half g_woutTh[CC*CC];                 // [512,512]  fp16 transposed

// ============================ PTX helpers ====================================
__device__ __forceinline__ uint32_t smem_u32(const void* p){
    uint32_t a;
    asm("{ .reg .u64 t; cvta.to.shared.u64 t, %1; cvt.u32.u64 %0, t; }"
        : "=r"(a) : "l"(p));
    return a;
}
__device__ __forceinline__ void cpa16(uint32_t dst, const void* src){
    asm volatile("cp.async.cg.shared.global [%0], [%1], 16;"
                 :: "r"(dst), "l"(src) : "memory");
}
__device__ __forceinline__ void cpa_commit(){
    asm volatile("cp.async.commit_group;" ::: "memory");
}
template<int N> __device__ __forceinline__ void cpa_wait(){
    asm volatile("cp.async.wait_group %0;" :: "n"(N) : "memory");
}
__device__ __forceinline__ void mma_f16(float* d, const uint32_t* a, const uint32_t* b){
    asm volatile("mma.sync.aligned.m16n8k16.row.col.f32.f16.f16.f32 "
        "{%0,%1,%2,%3}, {%4,%5,%6,%7}, {%8,%9}, {%0,%1,%2,%3};"
        : "+f"(d[0]), "+f"(d[1]), "+f"(d[2]), "+f"(d[3])
        : "r"(a[0]), "r"(a[1]), "r"(a[2]), "r"(a[3]), "r"(b[0]), "r"(b[1]));
}
__device__ __forceinline__ void ldsm4(uint32_t& r0, uint32_t& r1,
                                      uint32_t& r2, uint32_t& r3, uint32_t addr){
    asm volatile("ldmatrix.sync.aligned.m8n8.x4.shared.b16 {%0,%1,%2,%3}, [%4];"
        : "=r"(r0), "=r"(r1), "=r"(r2), "=r"(r3) : "r"(addr));
}
__device__ __forceinline__ void ldsm4t(uint32_t& r0, uint32_t& r1,
                                       uint32_t& r2, uint32_t& r3, uint32_t addr){
    asm volatile("ldmatrix.sync.aligned.m8n8.x4.trans.shared.b16 {%0,%1,%2,%3}, [%4];"
        : "=r"(r0), "=r"(r1), "=r"(r2), "=r"(r3) : "r"(addr));
}
__device__ __forceinline__ void ldsm2t(uint32_t& r0, uint32_t& r1, uint32_t addr){
    asm volatile("ldmatrix.sync.aligned.m8n8.x2.trans.shared.b16 {%0,%1}, [%2];"
        : "=r"(r0), "=r"(r1) : "r"(addr));
}

// ============================ mma.sync fp16 GEMM =============================
// D[M,Nn] = A[M,512] @ Bt[Nn,512]^T + bias, relu on cols < nrelu.
// CTA 128x128, 8 warps (4m x 2n), warp tile 32x64. BK=32, ldmatrix,
// 3-stage cp.async pipeline, one __syncthreads per K-tile, 2 CTA/SM.
#define GK    512
#define GBK   32
#define KPADH 40              // halves per row (80B stride; conflict-free LDSM)
#define NKT   (GK/GBK)        // 16 k-tiles
#define ROWB  (KPADH*2)       // 80 bytes per smem row
#define ASTG  (128*ROWB)      // 10240 bytes per stage per operand
#define NSTG  3
#define GSMEM (2*NSTG*ASTG)   // 61440 bytes total (3 stages x A,B)

template<typename OUT, bool STATS>
__global__ void __launch_bounds__(256, 2)
gemm_mma_kernel(const __half* __restrict__ A,
                const __half* __restrict__ Bt,
                const float* __restrict__ bias, OUT* __restrict__ Cout,
                int Nn, int nrelu)
{
    extern __shared__ __half dsm[];
    __shared__ float ssum[128], ssq[128];
    uint32_t base = smem_u32(dsm);
    const uint32_t BOFF = NSTG * ASTG;
    int tid = threadIdx.x;
    int wid = tid >> 5, lane = tid & 31;
    int gid = lane >> 2, tig = lane & 3;
    int warpM = (wid >> 1) * 32;
    int warpN = (wid & 1) * 64;
    int row0 = blockIdx.y * 128, col0 = blockIdx.x * 128;
    const __half* Ab = A  + (size_t)row0 * GK;
    const __half* Bb = Bt + (size_t)col0 * GK;

    if (STATS && tid < 128){ ssum[tid] = 0.f; ssq[tid] = 0.f; }

    int r0i = tid >> 2,          c0i = tid & 3;
    int r1i = (tid + 256) >> 2,  c1i = c0i;
    uint32_t aoff0 = (uint32_t)(r0i * ROWB + c0i * 16);
    uint32_t aoff1 = (uint32_t)(r1i * ROWB + c1i * 16);

    int aRow = warpM + (lane & 15);
    int aCol = (lane >> 4) * 8;
    int bRow = warpN + (lane >> 4) * 8 + (lane & 7);
    int bCol = ((lane >> 3) & 1) * 8;
    uint32_t aBase = (uint32_t)(aRow * ROWB + aCol * 2);
    uint32_t bBase = (uint32_t)(bRow * ROWB + bCol * 2);

    float acc[2][8][4];
    #pragma unroll
    for (int mi = 0; mi < 2; mi++)
        #pragma unroll
        for (int ni = 0; ni < 8; ni++)
            #pragma unroll
            for (int r = 0; r < 4; r++) acc[mi][ni][r] = 0.f;

    auto load_tile = [&](int t, int s){
        int k0 = t * GBK;
        uint32_t sa = base + s * ASTG;
        uint32_t sb = base + BOFF + s * ASTG;
        cpa16(sa + aoff0, Ab + (size_t)r0i * GK + k0 + c0i * 8);
        cpa16(sa + aoff1, Ab + (size_t)r1i * GK + k0 + c1i * 8);
        cpa16(sb + aoff0, Bb + (size_t)r0i * GK + k0 + c0i * 8);
        cpa16(sb + aoff1, Bb + (size_t)r1i * GK + k0 + c1i * 8);
    };

    load_tile(0, 0); cpa_commit();
    load_tile(1, 1); cpa_commit();

    for (int t = 0; t < NKT; t++){
        int s = t % NSTG;
        cpa_wait<1>();
        __syncthreads();
        if (t + 2 < NKT) load_tile(t + 2, (t + 2) % NSTG);
        cpa_commit();
        uint32_t sa = base + s * ASTG;
        uint32_t sb = base + BOFF + s * ASTG;
        #pragma unroll
        for (int ks = 0; ks < 2; ks++){
            int k0 = ks * 16;
            uint32_t a[2][4], bfr[8][2];
            #pragma unroll
            for (int mi = 0; mi < 2; mi++){
                uint32_t ad = sa + aBase + (uint32_t)(mi * 16 * ROWB + k0 * 2);
                ldsm4(a[mi][0], a[mi][1], a[mi][2], a[mi][3], ad);
            }
            #pragma unroll
            for (int p = 0; p < 4; p++){
                uint32_t bd = sb + bBase + (uint32_t)(p * 16 * ROWB + k0 * 2);
                ldsm4(bfr[2*p][0], bfr[2*p][1], bfr[2*p+1][0], bfr[2*p+1][1], bd);
            }
            #pragma unroll
            for (int mi = 0; mi < 2; mi++)
                #pragma unroll
                for (int ni = 0; ni < 8; ni++)
                    mma_f16(acc[mi][ni], a[mi], bfr[ni]);
        }
    }

    // epilogue: bias + optional relu (+ fused row stats)
    #pragma unroll
    for (int mi = 0; mi < 2; mi++){
        #pragma unroll
        for (int rr = 0; rr < 2; rr++){
            int rloc = warpM + mi * 16 + rr * 8 + gid;
            int r = row0 + rloc;
            float s = 0.f, sq = 0.f;
            #pragma unroll
            for (int ni = 0; ni < 8; ni++){
                int c = col0 + warpN + ni * 8 + tig * 2;
                float ox = acc[mi][ni][rr * 2 + 0] + bias[c + 0];
                float oy = acc[mi][ni][rr * 2 + 1] + bias[c + 1];
                if (c < nrelu){
                    ox = fmaxf(ox, 0.f);
                    oy = fmaxf(oy, 0.f);
                }
                if (STATS){
                    s  += ox + oy;
                    sq += ox * ox + oy * oy;
                }
                if constexpr (sizeof(OUT) == 4) {
                    float2 o{ox, oy};
                    *(float2*)((float*)Cout + (size_t)r * Nn + c) = o;
                } else {
                    __half2 o{__float2half(ox), __float2half(oy)};
                    *(__half2*)((__half*)Cout + (size_t)r * Nn + c) = o;
                }
            }
            if (STATS){
                s  += __shfl_xor_sync(0xffffffffu, s, 1);
                s  += __shfl_xor_sync(0xffffffffu, s, 2);
                sq += __shfl_xor_sync(0xffffffffu, sq, 1);
                sq += __shfl_xor_sync(0xffffffffu, sq, 2);
                if (tig == 0){
                    atomicAdd(&ssum[rloc], s);
                    atomicAdd(&ssq[rloc], sq);
                }
            }
        }
    }
    if (STATS){
        __syncthreads();
        if (tid < 128){
            atomicAdd(&g_musum[row0 + tid], ssum[tid]);
            atomicAdd(&g_sqsum[row0 + tid], ssq[tid]);
        }
    }
}

// ---------------- LN2 finalize: sums -> mu, rinv -----------------------------
__global__ void ln_fin_kernel()
{
    int i = blockIdx.x * blockDim.x + threadIdx.x;
    float mean = g_musum[i] * (1.0f / CC);
    float var  = g_sqsum[i] * (1.0f / CC) - mean * mean;
    g_mu[i]   = mean;
    g_rinv[i] = rsqrtf(var + EPSF);
}

// ---------------- merged weight transpose -> fp16 ----------------------------
__global__ void transpose_kernel(const float* __restrict__ qkvw,
                                 const float* __restrict__ outw,
                                 __half* __restrict__ qkvT,
                                 __half* __restrict__ outT)
{
    __shared__ float tile[32][33];
    const float* in; __half* outp; int Cc, bxi;
    if (blockIdx.x < 48){ in = qkvw; outp = qkvT; Cc = 1536; bxi = blockIdx.x; }
    else                { in = outw; outp = outT; Cc = 512;  bxi = blockIdx.x - 48; }
    int bx = bxi * 32, by = blockIdx.y * 32;
    int tx = threadIdx.x, ty = threadIdx.y;   // 32 x 8
    #pragma unroll
    for (int i = 0; i < 32; i += 8)
        tile[ty + i][tx] = in[(size_t)(by + ty + i) * Cc + bx + tx];
    __syncthreads();
    #pragma unroll
    for (int i = 0; i < 32; i += 8)
        outp[(size_t)(bx + ty + i) * 512 + by + tx] = __float2half(tile[tx][ty + i]);
}

// ---------------- layernorm over C=512 -> fp16 -------------------------------
__global__ void ln_kernel(const float* __restrict__ in,
                          const float* __restrict__ gamma,
                          const float* __restrict__ beta,
                          __half* __restrict__ out)
{
    int token = blockIdx.x;
    const float4* row = (const float4*)(in + (size_t)token * CC);
    int tid = threadIdx.x;
    float4 v = row[tid];
    float s  = v.x + v.y + v.z + v.w;
    float sq = v.x*v.x + v.y*v.y + v.z*v.z + v.w*v.w;
    #pragma unroll
    for (int o = 16; o; o >>= 1) {
        s  += __shfl_xor_sync(0xffffffffu, s,  o);
        sq += __shfl_xor_sync(0xffffffffu, sq, o);
    }
    __shared__ float ss[4], ssq[4];
    if ((tid & 31) == 0) { ss[tid >> 5] = s; ssq[tid >> 5] = sq; }
    __syncthreads();
    float ts = ss[0] + ss[1] + ss[2] + ss[3];
    float tq = ssq[0] + ssq[1] + ssq[2] + ssq[3];
    float mean = ts * (1.0f / CC);
    float var  = tq * (1.0f / CC) - mean * mean;
    float inv  = rsqrtf(var + EPSF);
    float4 g4 = ((const float4*)gamma)[tid];
    float4 b4 = ((const float4*)beta)[tid];
    __half2 p0{__float2half((v.x - mean) * inv * g4.x + b4.x),
               __float2half((v.y - mean) * inv * g4.y + b4.y)};
    __half2 p1{__float2half((v.z - mean) * inv * g4.z + b4.z),
               __float2half((v.w - mean) * inv * g4.w + b4.w)};
    uint2 pk;
    pk.x = *(uint32_t*)&p0;
    pk.y = *(uint32_t*)&p1;
    ((uint2*)(out + (size_t)token * CC))[tid] = pk;
}

// ---------------- zero scratch accumulators ---------------------------------
__global__ void zero_kernel()
{
    int i = blockIdx.x * blockDim.x + threadIdx.x;
    if (i < BB*HEADS*HD*HD) g_kv[i] = 0.f;
    if (i < BB*HEADS*HD)    g_ksum[i] = 0.f;
    if (i < NTOK)         { g_musum[i] = 0.f; g_sqsum[i] = 0.f; }
    if (i < CC)           { g_sum[i] = 0.f; g_sumsq[i] = 0.f; }
}

// ---------------- kv via mma: D[d][v'] = sum_n k[n][d]*vext[n][v'] -----------
// vext cols: 0-63 = v, col 64 = ones (-> ksum), 65-79 = 0.
// grid (64 bh, 8 chunks of 512 n), 256 thr = 8 warps (4d x 2v'), warp 16x40.
#define KVAPK 72   // ks row stride in halves (144B)
#define KVAPV 88   // vs row stride in halves (176B)
__global__ __launch_bounds__(256)
void kv_kernel(const __half* __restrict__ qkv)
{
    __shared__ __half ks[64][KVAPK];
    __shared__ __half vs[64][KVAPV];
    int bh = blockIdx.x;
    int b = bh >> 3, h = bh & 7;
    int tid = threadIdx.x;
    int wid = tid >> 5, lane = tid & 31;
    int gid = lane >> 2, tig = lane & 3;
    int warpM = (wid >> 1) * 16;     // d
    int warpN = (wid & 1) * 40;      // v'
    const __half* kbase = qkv + (size_t)(b*NN)*1536 +  512 + h*64;
    const __half* vbase = qkv + (size_t)(b*NN)*1536 + 1024 + h*64;
    uint32_t ksb = smem_u32(&ks[0][0]);
    uint32_t vsb = smem_u32(&vs[0][0]);

    // init vext cols 64-79 once: col64 = 1, rest 0
    for (int i = tid; i < 64*16; i += 256)
        vs[i >> 4][64 + (i & 15)] = __float2half((i & 15) == 0 ? 1.0f : 0.0f);

    // ldmatrix.trans lane address offsets
    int g = lane >> 3, l = lane & 7;
    // A regs: a0=(m0-7,k0-7) a1=(m8-15,k0-7) a2=(m0-7,k8-15) a3=(m8-15,k8-15)
    uint32_t aoff = (uint32_t)((((g >> 1) * 8) + l) * KVAPK + warpM + (g & 1) * 8) * 2;
    // B x4 regs: b[2p][0]=(v0-7,k0-7) b[2p][1]=(v0-7,k8-15) b[2p+1][0]=(v8-15,k0-7) ...
    uint32_t boff = (uint32_t)((((g & 1) * 8) + l) * KVAPV + warpN + (g >> 1) * 8) * 2;
    int l2 = lane & 15;
    uint32_t b2off = (uint32_t)((((l2 >> 3) * 8) + (l2 & 7)) * KVAPV + warpN + 32) * 2;

    float acc[5][4];
    #pragma unroll
    for (int ni = 0; ni < 5; ni++)
        #pragma unroll
        for (int r = 0; r < 4; r++) acc[ni][r] = 0.f;

    int r0i = tid >> 3,           c0i = (tid & 7) * 8;
    int r1i = (tid + 256) >> 3,   c1i = c0i;

    int n0 = blockIdx.y * 512;
    for (int s = 0; s < 8; s++){
        int nb = n0 + s * 64;
        __syncthreads();
        cpa16(ksb + (uint32_t)(r0i*KVAPK + c0i)*2, kbase + (size_t)(nb + r0i)*1536 + c0i);
        cpa16(ksb + (uint32_t)(r1i*KVAPK + c1i)*2, kbase + (size_t)(nb + r1i)*1536 + c1i);
        cpa16(vsb + (uint32_t)(r0i*KVAPV + c0i)*2, vbase + (size_t)(nb + r0i)*1536 + c0i);
        cpa16(vsb + (uint32_t)(r1i*KVAPV + c1i)*2, vbase + (size_t)(nb + r1i)*1536 + c1i);
        cpa_commit();
        cpa_wait<0>();
        __syncthreads();
        #pragma unroll
        for (int kk = 0; kk < 4; kk++){
            uint32_t a[4], bf[5][2];
            ldsm4t(a[0], a[1], a[2], a[3],
                   ksb + aoff + (uint32_t)(kk * 16 * KVAPK) * 2);
            #pragma unroll
            for (int p = 0; p < 2; p++)
                ldsm4t(bf[2*p][0], bf[2*p][1], bf[2*p+1][0], bf[2*p+1][1],
                       vsb + boff + (uint32_t)(p * 16 + kk * 16 * KVAPV) * 2);
            ldsm2t(bf[4][0], bf[4][1],
                   vsb + b2off + (uint32_t)(kk * 16 * KVAPV) * 2);
            #pragma unroll
            for (int ni = 0; ni < 5; ni++)
                mma_f16(acc[ni], a, bf[ni]);
        }
    }

    float* kvout = g_kv + bh * 4096;
    #pragma unroll
    for (int ni = 0; ni < 5; ni++){
        #pragma unroll
        for (int rr = 0; rr < 2; rr++){
            int r = warpM + rr * 8 + gid;
            int c = warpN + ni * 8 + tig * 2;
            if (c < 64){
                atomicAdd(&kvout[r * 64 + c],     acc[ni][rr*2+0]);
                atomicAdd(&kvout[r * 64 + c + 1], acc[ni][rr*2+1]);
            } else if (c == 64){
                atomicAdd(&g_ksum[bh * 64 + r], acc[ni][rr*2+0]);
            }
        }
    }
}

// ---------------- kvfin: build fp16 B matrix [80][64] per bh -----------------
__global__ void kvfin_kernel()
{
    int bh = blockIdx.x;
    int tid = threadIdx.x;
    for (int i = tid; i < 80*64; i += 256){
        int n = i >> 6, d = i & 63;
        float v;
        if (n < 64)      v = g_kv[bh * 4096 + d * 64 + n];
        else if (n == 64) v = fmaxf(g_ksum[bh * 64 + d], CLAMPF);
        else             v = 0.f;
        g_kvbh[bh * 5120 + i] = __float2half(v);
    }
}

// ---------------- attn via mma: D = q @ [kv | norms]^T, divide, -> fp16 ------
#define APAD 72
__global__ __launch_bounds__(256)
void attn_kernel(const __half* __restrict__ qkv, __half* __restrict__ attn)
{
    __shared__ __half qs[128][APAD];
    __shared__ __half bs[80][APAD];
    int bh = blockIdx.x;
    int b = bh >> 3, h = bh & 7;
    int tok0 = blockIdx.y * 128;
    int tid = threadIdx.x;
    int wid = tid >> 5, lane = tid & 31;
    int gid = lane >> 2, tig = lane & 3;
    const __half* qbase = qkv + (size_t)(b*NN + tok0) * 1536 + h*64;
    const __half* kvb = g_kvbh + bh * 5120;

    uint32_t qsb = smem_u32(&qs[0][0]);
    uint32_t bsb = smem_u32(&bs[0][0]);
    #pragma unroll
    for (int i = 0; i < 4; i++){
        int idx = tid + i * 256;
        int row = idx >> 3, c = (idx & 7) * 8;
        cpa16(qsb + (uint32_t)(row * APAD + c) * 2, qbase + (size_t)row * 1536 + c);
    }
    #pragma unroll
    for (int i = 0; i < 3; i++){
        int idx = tid + i * 256;
        if (idx < 640){
            int row = idx >> 3, c = (idx & 7) * 8;
            cpa16(bsb + (uint32_t)(row * APAD + c) * 2, kvb + row * 64 + c);
        }
    }
    cpa_commit();
    cpa_wait<0>();
    __syncthreads();

    int aRow = wid * 16 + (lane & 15);
    int aCol = (lane >> 4) * 8;
    int bRow = (lane >> 4) * 8 + (lane & 7);
    int bCol = ((lane >> 3) & 1) * 8;
    uint32_t aBase = qsb + (uint32_t)(aRow * APAD + aCol) * 2;
    uint32_t bBase = bsb + (uint32_t)(bRow * APAD + bCol) * 2;

    float acc[10][4];
    #pragma unroll
    for (int ni = 0; ni < 10; ni++)
        #pragma unroll
        for (int r = 0; r < 4; r++) acc[ni][r] = 0.f;

    #pragma unroll
    for (int ks = 0; ks < 4; ks++){
        int k0 = ks * 16;
        uint32_t a[4], bf[10][2];
        ldsm4(a[0], a[1], a[2], a[3], aBase + (uint32_t)(k0 * 2));
        #pragma unroll
        for (int p = 0; p < 5; p++){
            uint32_t bd = bBase + (uint32_t)(p * 16 * APAD + k0) * 2;
            ldsm4(bf[2*p][0], bf[2*p][1], bf[2*p+1][0], bf[2*p+1][1], bd);
        }
        #pragma unroll
        for (int ni = 0; ni < 9; ni++)
            mma_f16(acc[ni], a, bf[ni]);
    }

    float d0 = __shfl_sync(0xffffffffu, acc[8][0], lane & 0x1C);
    float d8 = __shfl_sync(0xffffffffu, acc[8][2], lane & 0x1C);
    float i0 = 1.0f / fmaxf(d0, CLAMPF);
    float i8 = 1.0f / fmaxf(d8, CLAMPF);

    __half* obase = attn + (size_t)(b*NN + tok0 + wid*16) * CC + h*64;
    #pragma unroll
    for (int ni = 0; ni < 8; ni++){
        int c = ni * 8 + tig * 2;
        __half2 o0{__float2half(acc[ni][0] * i0), __float2half(acc[ni][1] * i0)};
        __half2 o8{__float2half(acc[ni][2] * i8), __float2half(acc[ni][3] * i8)};
        *(__half2*)(obase + (size_t)gid * CC + c) = o0;
        *(__half2*)(obase + (size_t)(gid + 8) * CC + c) = o8;
    }
}

// ---------------- conv1: fused LN2-apply + dw7x7 + gelu + bn stats -----------
__global__ __launch_bounds__(256)
void conv1_kernel(const __half* __restrict__ ap, const float* __restrict__ cw,
                  const float* __restrict__ cb, const float* __restrict__ lg,
                  const float* __restrict__ lb)
{
    int b  = blockIdx.z;
    int c0 = blockIdx.y * 32;
    int h0 = (blockIdx.x >> 3) * 8;
    int w0 = (blockIdx.x & 7) * 8;
    __shared__ float ins[14][14][32];
    __shared__ float ws[32][49];
    __shared__ float sg[32], sb[32];
    __shared__ float rsum[8][32], rsq[8][32];
    int tid = threadIdx.x;
    if (tid < 32){ sg[tid] = lg[c0 + tid]; sb[tid] = lb[c0 + tid]; }
    for (int i = tid; i < 32 * 49; i += 256)
        ws[i / 49][i % 49] = cw[(c0 + i / 49) * 49 + (i % 49)];
    __syncthreads();
    for (int i = tid; i < 14 * 14 * 16; i += 256) {
        int ic = (i & 15) * 2; int pos = i >> 4;
        int iw = pos % 14, ih = pos / 14;
        int gh = h0 + ih - 3, gw = w0 + iw - 3;
        float vx = 0.f, vy = 0.f;
        if (gh >= 0 && gh < HH && gw >= 0 && gw < WW){
            size_t tok = (size_t)(b*NN) + gh*WW + gw;
            __half2 a2 = *(const __half2*)(ap + tok * CC + c0 + ic);
            float2 af = __half22float2(a2);
            float mu = g_mu[tok], ri = g_rinv[tok];
            vx = (af.x - mu) * ri * sg[ic]     + sb[ic];
            vy = (af.y - mu) * ri * sg[ic + 1] + sb[ic + 1];
        }
        ins[ih][iw][ic]     = vx;
        ins[ih][iw][ic + 1] = vy;
    }
    __syncthreads();
    int oc = tid & 31;
    int ow = tid >> 5;
    float wr[49];
    #pragma unroll
    for (int j = 0; j < 49; j++) wr[j] = ws[oc][j];
    float bias = cb[c0 + oc];
    float acc[8];
    #pragma unroll
    for (int oh = 0; oh < 8; oh++) acc[oh] = bias;
    #pragma unroll
    for (int ih = 0; ih < 14; ih++){
        float v[7];
        #pragma unroll
        for (int dw = 0; dw < 7; dw++) v[dw] = ins[ih][ow + dw][oc];
        #pragma unroll
        for (int oh = 0; oh < 8; oh++){
            int dh = ih - oh;
            if (dh >= 0 && dh < 7){
                #pragma unroll
                for (int dw = 0; dw < 7; dw++)
                    acc[oh] += v[dw] * wr[dh * 7 + dw];
            }
        }
    }
    float psum = 0.f, psq = 0.f;
    #pragma unroll
    for (int oh = 0; oh < 8; oh++){
        float yv = acc[oh] * normcdff(acc[oh]);
        g_y[((size_t)(b*NN) + (h0+oh)*WW + (w0+ow)) * CC + c0 + oc] = __float2half(yv);
        psum += yv; psq += yv * yv;
    }
    rsum[ow][oc] = psum; rsq[ow][oc] = psq;
    __syncthreads();
    if (tid < 32) {
        float s = 0.f, q = 0.f;
        #pragma unroll
        for (int i = 0; i < 8; i++) { s += rsum[i][tid]; q += rsq[i][tid]; }
        atomicAdd(&g_sum[c0 + tid], s);
        atomicAdd(&g_sumsq[c0 + tid], q);
    }
}

// ---------------- conv2: BN-apply + depthwise 7x7 + triple residual ----------
__global__ __launch_bounds__(256)
void conv2_kernel(const float* __restrict__ x, const float* __restrict__ cw,
                  const float* __restrict__ cb, const float* __restrict__ bng,
                  const float* __restrict__ bnb, float* __restrict__ out)
{
    int b  = blockIdx.z;
    int c0 = blockIdx.y * 32;
    int h0 = (blockIdx.x >> 3) * 8;
    int w0 = (blockIdx.x & 7) * 8;
    __shared__ float ins[14][14][32];
    __shared__ float ws[32][49];
    __shared__ float scs[32], shs[32];
    int tid = threadIdx.x;
    if (tid < 32) {
        int c = c0 + tid;
        float m   = g_sum[c]   * (1.0f / (float)NTOK);
        float var = g_sumsq[c] * (1.0f / (float)NTOK) - m * m;
        float inv = rsqrtf(var + EPSF);
        float sc = bng[c] * inv;
        scs[tid] = sc;
        shs[tid] = bnb[c] - m * sc;
    }
    for (int i = tid; i < 32 * 49; i += 256)
        ws[i / 49][i % 49] = cw[(c0 + i / 49) * 49 + (i % 49)];
    __syncthreads();
    for (int i = tid; i < 14 * 14 * 16; i += 256) {
        int ic = (i & 15) * 2; int pos = i >> 4;
        int iw = pos % 14, ih = pos / 14;
        int gh = h0 + ih - 3, gw = w0 + iw - 3;
        float vx = 0.f, vy = 0.f;
        if (gh >= 0 && gh < HH && gw >= 0 && gw < WW){
            __half2 y2 = *(const __half2*)(&g_y[((size_t)(b*NN) + gh*WW + gw) * CC + c0 + ic]);
            float2 yf = __half22float2(y2);
            vx = yf.x * scs[ic]     + shs[ic];
            vy = yf.y * scs[ic + 1] + shs[ic + 1];
        }
        ins[ih][iw][ic]     = vx;
        ins[ih][iw][ic + 1] = vy;
    }
    __syncthreads();
    int oc = tid & 31;
    int ow = tid >> 5;
    float wr[49];
    #pragma unroll
    for (int j = 0; j < 49; j++) wr[j] = ws[oc][j];
    float bias = cb[c0 + oc];
    float acc[8];
    #pragma unroll
    for (int oh = 0; oh < 8; oh++) acc[oh] = bias;
    #pragma unroll
    for (int ih = 0; ih < 14; ih++){
        float v[7];
        #pragma unroll
        for (int dw = 0; dw < 7; dw++) v[dw] = ins[ih][ow + dw][oc];
        #pragma unroll
        for (int oh = 0; oh < 8; oh++){
            int dh = ih - oh;
            if (dh >= 0 && dh < 7){
                #pragma unroll
                for (int dw = 0; dw < 7; dw++)
                    acc[oh] += v[dw] * wr[dh * 7 + dw];
            }
        }
    }
    #pragma unroll
    for (int oh = 0; oh < 8; oh++){
        size_t idx = ((size_t)(b*NN) + (h0+oh)*WW + (w0+ow)) * CC + c0 + oc;
        out[idx] = x[idx] + __half2float(g_attnproj[idx]) + acc[oh];
    }
}

// ---------------- launch ----------------------------------------------------
extern "C" void kernel_launch(void* const* d_in, const int* in_sizes, int n_in,
                              void* d_out, int out_size)
{
    const float* x      = (const float*)d_in[0];
    const float* qkv_w  = (const float*)d_in[1];
    const float* qkv_b  = (const float*)d_in[2];
    const float* out_w  = (const float*)d_in[3];
    const float* out_b  = (const float*)d_in[4];
    const float* pre_g  = (const float*)d_in[5];
    const float* pre_b  = (const float*)d_in[6];
    const float* lcm_g  = (const float*)d_in[7];
    const float* lcm_b  = (const float*)d_in[8];
    const float* ci_w   = (const float*)d_in[9];
    const float* ci_b   = (const float*)d_in[10];
    const float* bn_g   = (const float*)d_in[11];
    const float* bn_b   = (const float*)d_in[12];
    const float* co_w   = (const float*)d_in[13];
    const float* co_b   = (const float*)d_in[14];
    float* out = (float*)d_out;

    __half *p_normedh, *p_qkvh, *p_attnh, *p_attnproj, *p_wqkvTh, *p_woutTh;
    cudaGetSymbolAddress((void**)&p_normedh,  g_normedh);
    cudaGetSymbolAddress((void**)&p_qkvh,     g_qkvh);
    cudaGetSymbolAddress((void**)&p_attnh,    g_attnh);
    cudaGetSymbolAddress((void**)&p_attnproj, g_attnproj);
    cudaGetSymbolAddress((void**)&p_wqkvTh,   g_wqkvTh);
    cudaGetSymbolAddress((void**)&p_woutTh,   g_woutTh);

    cudaFuncSetAttribute(gemm_mma_kernel<__half, false>,
        cudaFuncAttributeMaxDynamicSharedMemorySize, GSMEM);
    cudaFuncSetAttribute(gemm_mma_kernel<__half, true>,
        cudaFuncAttributeMaxDynamicSharedMemorySize, GSMEM);

    // 1. merged weight transpose ([K,N] -> [N,K], fp16)
    transpose_kernel<<<dim3(64, 16), dim3(32,8)>>>(qkv_w, out_w, p_wqkvTh, p_woutTh);
    // 2. zero accumulators
    zero_kernel<<<(BB*HEADS*HD*HD + 255) / 256, 256>>>();
    // 3. pre-layernorm -> fp16
    ln_kernel<<<NTOK, 128>>>(x, pre_g, pre_b, p_normedh);
    // 4. qkv gemm (3-stage pipeline, cp.async.cg) + relu on cols [0,1024)
    gemm_mma_kernel<__half, false><<<dim3(1536/128, NTOK/128), 256, GSMEM>>>(
        p_normedh, p_wqkvTh, qkv_b, p_qkvh, 1536, 1024);
    // 5. kv outer-product + ksum via mma (ones-column)
    kv_kernel<<<dim3(BB*HEADS, 8), 256>>>(p_qkvh);
    // 6. build fp16 [kv | norms] B matrices
    kvfin_kernel<<<BB*HEADS, 256>>>();
    // 7. attention apply via mma -> fp16
    attn_kernel<<<dim3(BB*HEADS, 32), 256>>>(p_qkvh, p_attnh);
    // 8. output projection + fused LN2 row sums
    gemm_mma_kernel<__half, true><<<dim3(CC/128, NTOK/128), 256, GSMEM>>>(
        p_attnh, p_woutTh, out_b, p_attnproj, 512, 0);
    // 9. LN2 finalize (sums -> mu, rinv)
    ln_fin_kernel<<<NTOK/256, 256>>>();
    // 10. conv1 (LN2-apply fused) + gelu + bn stats -> fp16 y
    conv1_kernel<<<dim3(64, CC/32, BB), 256>>>(p_attnproj, ci_w, ci_b, lcm_g, lcm_b);
    // 11. bn apply + conv2 + triple residual -> out
    conv2_kernel<<<dim3(64, CC/32, BB), 256>>>(x, co_w, co_b, bn_g, bn_b, out);
}

// round 17
// speedup vs baseline: 1.7182x; 1.0031x over previous
#include <cuda_runtime.h>
#include <cuda_fp16.h>
#include <math.h>
#include <cstdint>

#define BB    8
#define NN    4096
#define CC    512
#define NTOK  (BB*NN)        // 32768 tokens
#define HEADS 8
#define HD    64
#define HH    64
#define WW    64
#define EPSF  1e-5f
#define CLAMPF 100.0f

// ---------------- scratch (static device globals; no runtime alloc) ----------
__device__ __half g_normedh[NTOK*CC];              // 32 MB (GEMM1 A)
__device__ __half g_qkvh[(size_t)NTOK*3*CC];       // 96 MB (GEMM1 out, fp16)
__device__ __half g_attnh[NTOK*CC];                // 32 MB (GEMM2 A)
__device__ __half g_attnproj[NTOK*CC];             // 32 MB (GEMM2 out, fp16)
__device__ __half g_y[NTOK*CC];                    // 32 MB (conv1 out, fp16)
__device__ float g_mu[NTOK];                       // LN2 per-token mean
__device__ float g_rinv[NTOK];                     // LN2 per-token 1/std
__device__ float g_musum[NTOK];                    // LN2 partial row sums
__device__ float g_sqsum[NTOK];
__device__ float g_kv[BB*HEADS*HD*HD];
__device__ float g_ksum[BB*HEADS*HD];
__device__ __half g_kvbh[BB*HEADS*80*64];          // fp16 [n(v)|norms|pad][d] per bh
__device__ float g_sum[CC];
__device__ float g_sumsq[CC];
__device__ __half g_wqkvTh[3*CC*CC];               // [1536,512] fp16 transposed
__device__ __half g_woutTh[CC*CC];                 // [512,512]  fp16 transposed

// ============================ PTX helpers ====================================
__device__ __forceinline__ uint32_t smem_u32(const void* p){
    uint32_t a;
    asm("{ .reg .u64 t; cvta.to.shared.u64 t, %1; cvt.u32.u64 %0, t; }"
        : "=r"(a) : "l"(p));
    return a;
}
__device__ __forceinline__ void cpa16(uint32_t dst, const void* src){
    asm volatile("cp.async.cg.shared.global [%0], [%1], 16;"
                 :: "r"(dst), "l"(src) : "memory");
}
__device__ __forceinline__ void cpa_commit(){
    asm volatile("cp.async.commit_group;" ::: "memory");
}
template<int N> __device__ __forceinline__ void cpa_wait(){
    asm volatile("cp.async.wait_group %0;" :: "n"(N) : "memory");
}
__device__ __forceinline__ void mma_f16(float* d, const uint32_t* a, const uint32_t* b){
    asm volatile("mma.sync.aligned.m16n8k16.row.col.f32.f16.f16.f32 "
        "{%0,%1,%2,%3}, {%4,%5,%6,%7}, {%8,%9}, {%0,%1,%2,%3};"
        : "+f"(d[0]), "+f"(d[1]), "+f"(d[2]), "+f"(d[3])
        : "r"(a[0]), "r"(a[1]), "r"(a[2]), "r"(a[3]), "r"(b[0]), "r"(b[1]));
}
__device__ __forceinline__ void ldsm4(uint32_t& r0, uint32_t& r1,
                                      uint32_t& r2, uint32_t& r3, uint32_t addr){
    asm volatile("ldmatrix.sync.aligned.m8n8.x4.shared.b16 {%0,%1,%2,%3}, [%4];"
        : "=r"(r0), "=r"(r1), "=r"(r2), "=r"(r3) : "r"(addr));
}
__device__ __forceinline__ void ldsm4t(uint32_t& r0, uint32_t& r1,
                                       uint32_t& r2, uint32_t& r3, uint32_t addr){
    asm volatile("ldmatrix.sync.aligned.m8n8.x4.trans.shared.b16 {%0,%1,%2,%3}, [%4];"
        : "=r"(r0), "=r"(r1), "=r"(r2), "=r"(r3) : "r"(addr));
}
__device__ __forceinline__ void ldsm2t(uint32_t& r0, uint32_t& r1, uint32_t addr){
    asm volatile("ldmatrix.sync.aligned.m8n8.x2.trans.shared.b16 {%0,%1}, [%2];"
        : "=r"(r0), "=r"(r1) : "r"(addr));
}

// ============================ mma.sync fp16 GEMM =============================
// D[M,Nn] = A[M,512] @ Bt[Nn,512]^T + bias, relu on cols < nrelu.
// CTA 128x128, 8 warps (4m x 2n), warp tile 32x64. BK=32, ldmatrix,
// 3-stage cp.async pipeline, one __syncthreads per K-tile, 2 CTA/SM.
#define GK    512
#define GBK   32
#define KPADH 40              // halves per row (80B stride; conflict-free LDSM)
#define NKT   (GK/GBK)        // 16 k-tiles
#define ROWB  (KPADH*2)       // 80 bytes per smem row
#define ASTG  (128*ROWB)      // 10240 bytes per stage per operand
#define NSTG  3
#define GSMEM (2*NSTG*ASTG)   // 61440 bytes total (3 stages x A,B)

template<typename OUT, bool STATS>
__global__ void __launch_bounds__(256, 2)
gemm_mma_kernel(const __half* __restrict__ A,
                const __half* __restrict__ Bt,
                const float* __restrict__ bias, OUT* __restrict__ Cout,
                int Nn, int nrelu)
{
    extern __shared__ __half dsm[];
    __shared__ float ssum[128], ssq[128];
    uint32_t base = smem_u32(dsm);
    const uint32_t BOFF = NSTG * ASTG;
    int tid = threadIdx.x;
    int wid = tid >> 5, lane = tid & 31;
    int gid = lane >> 2, tig = lane & 3;
    int warpM = (wid >> 1) * 32;
    int warpN = (wid & 1) * 64;
    int row0 = blockIdx.y * 128, col0 = blockIdx.x * 128;
    const __half* Ab = A  + (size_t)row0 * GK;
    const __half* Bb = Bt + (size_t)col0 * GK;

    if (STATS && tid < 128){ ssum[tid] = 0.f; ssq[tid] = 0.f; }

    int r0i = tid >> 2,          c0i = tid & 3;
    int r1i = (tid + 256) >> 2,  c1i = c0i;
    uint32_t aoff0 = (uint32_t)(r0i * ROWB + c0i * 16);
    uint32_t aoff1 = (uint32_t)(r1i * ROWB + c1i * 16);

    int aRow = warpM + (lane & 15);
    int aCol = (lane >> 4) * 8;
    int bRow = warpN + (lane >> 4) * 8 + (lane & 7);
    int bCol = ((lane >> 3) & 1) * 8;
    uint32_t aBase = (uint32_t)(aRow * ROWB + aCol * 2);
    uint32_t bBase = (uint32_t)(bRow * ROWB + bCol * 2);

    float acc[2][8][4];
    #pragma unroll
    for (int mi = 0; mi < 2; mi++)
        #pragma unroll
        for (int ni = 0; ni < 8; ni++)
            #pragma unroll
            for (int r = 0; r < 4; r++) acc[mi][ni][r] = 0.f;

    auto load_tile = [&](int t, int s){
        int k0 = t * GBK;
        uint32_t sa = base + s * ASTG;
        uint32_t sb = base + BOFF + s * ASTG;
        cpa16(sa + aoff0, Ab + (size_t)r0i * GK + k0 + c0i * 8);
        cpa16(sa + aoff1, Ab + (size_t)r1i * GK + k0 + c1i * 8);
        cpa16(sb + aoff0, Bb + (size_t)r0i * GK + k0 + c0i * 8);
        cpa16(sb + aoff1, Bb + (size_t)r1i * GK + k0 + c1i * 8);
    };

    load_tile(0, 0); cpa_commit();
    load_tile(1, 1); cpa_commit();

    for (int t = 0; t < NKT; t++){
        int s = t % NSTG;
        cpa_wait<1>();
        __syncthreads();
        if (t + 2 < NKT) load_tile(t + 2, (t + 2) % NSTG);
        cpa_commit();
        uint32_t sa = base + s * ASTG;
        uint32_t sb = base + BOFF + s * ASTG;
        #pragma unroll
        for (int ks = 0; ks < 2; ks++){
            int k0 = ks * 16;
            uint32_t a[2][4], bfr[8][2];
            #pragma unroll
            for (int mi = 0; mi < 2; mi++){
                uint32_t ad = sa + aBase + (uint32_t)(mi * 16 * ROWB + k0 * 2);
                ldsm4(a[mi][0], a[mi][1], a[mi][2], a[mi][3], ad);
            }
            #pragma unroll
            for (int p = 0; p < 4; p++){
                uint32_t bd = sb + bBase + (uint32_t)(p * 16 * ROWB + k0 * 2);
                ldsm4(bfr[2*p][0], bfr[2*p][1], bfr[2*p+1][0], bfr[2*p+1][1], bd);
            }
            #pragma unroll
            for (int mi = 0; mi < 2; mi++)
                #pragma unroll
                for (int ni = 0; ni < 8; ni++)
                    mma_f16(acc[mi][ni], a[mi], bfr[ni]);
        }
    }

    // epilogue: bias + optional relu (+ fused row stats)
    #pragma unroll
    for (int mi = 0; mi < 2; mi++){
        #pragma unroll
        for (int rr = 0; rr < 2; rr++){
            int rloc = warpM + mi * 16 + rr * 8 + gid;
            int r = row0 + rloc;
            float s = 0.f, sq = 0.f;
            #pragma unroll
            for (int ni = 0; ni < 8; ni++){
                int c = col0 + warpN + ni * 8 + tig * 2;
                float ox = acc[mi][ni][rr * 2 + 0] + bias[c + 0];
                float oy = acc[mi][ni][rr * 2 + 1] + bias[c + 1];
                if (c < nrelu){
                    ox = fmaxf(ox, 0.f);
                    oy = fmaxf(oy, 0.f);
                }
                if (STATS){
                    s  += ox + oy;
                    sq += ox * ox + oy * oy;
                }
                if constexpr (sizeof(OUT) == 4) {
                    float2 o{ox, oy};
                    *(float2*)((float*)Cout + (size_t)r * Nn + c) = o;
                } else {
                    __half2 o{__float2half(ox), __float2half(oy)};
                    *(__half2*)((__half*)Cout + (size_t)r * Nn + c) = o;
                }
            }
            if (STATS){
                s  += __shfl_xor_sync(0xffffffffu, s, 1);
                s  += __shfl_xor_sync(0xffffffffu, s, 2);
                sq += __shfl_xor_sync(0xffffffffu, sq, 1);
                sq += __shfl_xor_sync(0xffffffffu, sq, 2);
                if (tig == 0){
                    atomicAdd(&ssum[rloc], s);
                    atomicAdd(&ssq[rloc], sq);
                }
            }
        }
    }
    if (STATS){
        __syncthreads();
        if (tid < 128){
            atomicAdd(&g_musum[row0 + tid], ssum[tid]);
            atomicAdd(&g_sqsum[row0 + tid], ssq[tid]);
        }
    }
}

// ---------------- LN2 finalize: sums -> mu, rinv -----------------------------
__global__ void ln_fin_kernel()
{
    int i = blockIdx.x * blockDim.x + threadIdx.x;
    float mean = g_musum[i] * (1.0f / CC);
    float var  = g_sqsum[i] * (1.0f / CC) - mean * mean;
    g_mu[i]   = mean;
    g_rinv[i] = rsqrtf(var + EPSF);
}

// ---------------- merged weight transpose -> fp16 ----------------------------
__global__ void transpose_kernel(const float* __restrict__ qkvw,
                                 const float* __restrict__ outw,
                                 __half* __restrict__ qkvT,
                                 __half* __restrict__ outT)
{
    __shared__ float tile[32][33];
    const float* in; __half* outp; int Cc, bxi;
    if (blockIdx.x < 48){ in = qkvw; outp = qkvT; Cc = 1536; bxi = blockIdx.x; }
    else                { in = outw; outp = outT; Cc = 512;  bxi = blockIdx.x - 48; }
    int bx = bxi * 32, by = blockIdx.y * 32;
    int tx = threadIdx.x, ty = threadIdx.y;   // 32 x 8
    #pragma unroll
    for (int i = 0; i < 32; i += 8)
        tile[ty + i][tx] = in[(size_t)(by + ty + i) * Cc + bx + tx];
    __syncthreads();
    #pragma unroll
    for (int i = 0; i < 32; i += 8)
        outp[(size_t)(bx + ty + i) * 512 + by + tx] = __float2half(tile[tx][ty + i]);
}

// ---------------- layernorm over C=512 -> fp16 -------------------------------
__global__ void ln_kernel(const float* __restrict__ in,
                          const float* __restrict__ gamma,
                          const float* __restrict__ beta,
                          __half* __restrict__ out)
{
    int token = blockIdx.x;
    const float4* row = (const float4*)(in + (size_t)token * CC);
    int tid = threadIdx.x;
    float4 v = row[tid];
    float s  = v.x + v.y + v.z + v.w;
    float sq = v.x*v.x + v.y*v.y + v.z*v.z + v.w*v.w;
    #pragma unroll
    for (int o = 16; o; o >>= 1) {
        s  += __shfl_xor_sync(0xffffffffu, s,  o);
        sq += __shfl_xor_sync(0xffffffffu, sq, o);
    }
    __shared__ float ss[4], ssq[4];
    if ((tid & 31) == 0) { ss[tid >> 5] = s; ssq[tid >> 5] = sq; }
    __syncthreads();
    float ts = ss[0] + ss[1] + ss[2] + ss[3];
    float tq = ssq[0] + ssq[1] + ssq[2] + ssq[3];
    float mean = ts * (1.0f / CC);
    float var  = tq * (1.0f / CC) - mean * mean;
    float inv  = rsqrtf(var + EPSF);
    float4 g4 = ((const float4*)gamma)[tid];
    float4 b4 = ((const float4*)beta)[tid];
    __half2 p0{__float2half((v.x - mean) * inv * g4.x + b4.x),
               __float2half((v.y - mean) * inv * g4.y + b4.y)};
    __half2 p1{__float2half((v.z - mean) * inv * g4.z + b4.z),
               __float2half((v.w - mean) * inv * g4.w + b4.w)};
    uint2 pk;
    pk.x = *(uint32_t*)&p0;
    pk.y = *(uint32_t*)&p1;
    ((uint2*)(out + (size_t)token * CC))[tid] = pk;
}

// ---------------- zero scratch accumulators ---------------------------------
__global__ void zero_kernel()
{
    int i = blockIdx.x * blockDim.x + threadIdx.x;
    if (i < BB*HEADS*HD*HD) g_kv[i] = 0.f;
    if (i < BB*HEADS*HD)    g_ksum[i] = 0.f;
    if (i < NTOK)         { g_musum[i] = 0.f; g_sqsum[i] = 0.f; }
    if (i < CC)           { g_sum[i] = 0.f; g_sumsq[i] = 0.f; }
}

// ---------------- kv via mma, 2-stage pipeline -------------------------------
// D[d][v'] = sum_n k[n][d]*vext[n][v']; vext col 64 = ones (-> ksum).
// grid (64 bh, 8 chunks of 512 n), 256 thr = 8 warps (4d x 2v'), warp 16x40.
#define KVAPK 72   // ks row stride in halves (144B)
#define KVAPV 88   // vs row stride in halves (176B)
__global__ __launch_bounds__(256)
void kv_kernel(const __half* __restrict__ qkv)
{
    __shared__ __half ks[2][64][KVAPK];
    __shared__ __half vs[2][64][KVAPV];
    int bh = blockIdx.x;
    int b = bh >> 3, h = bh & 7;
    int tid = threadIdx.x;
    int wid = tid >> 5, lane = tid & 31;
    int gid = lane >> 2, tig = lane & 3;
    int warpM = (wid >> 1) * 16;     // d
    int warpN = (wid & 1) * 40;      // v'
    const __half* kbase = qkv + (size_t)(b*NN)*1536 +  512 + h*64;
    const __half* vbase = qkv + (size_t)(b*NN)*1536 + 1024 + h*64;
    uint32_t ksb0 = smem_u32(&ks[0][0][0]);
    uint32_t vsb0 = smem_u32(&vs[0][0][0]);
    const uint32_t KSTG = 64 * KVAPK * 2;
    const uint32_t VSTG = 64 * KVAPV * 2;

    // init vext cols 64-79 in BOTH stages: col64 = 1, rest 0 (loads never touch)
    for (int i = tid; i < 64*16; i += 256){
        __half v = __float2half((i & 15) == 0 ? 1.0f : 0.0f);
        vs[0][i >> 4][64 + (i & 15)] = v;
        vs[1][i >> 4][64 + (i & 15)] = v;
    }

    // ldmatrix.trans lane address offsets
    int g = lane >> 3, l = lane & 7;
    uint32_t aoff = (uint32_t)((((g >> 1) * 8) + l) * KVAPK + warpM + (g & 1) * 8) * 2;
    uint32_t boff = (uint32_t)((((g & 1) * 8) + l) * KVAPV + warpN + (g >> 1) * 8) * 2;
    int l2 = lane & 15;
    uint32_t b2off = (uint32_t)((((l2 >> 3) * 8) + (l2 & 7)) * KVAPV + warpN + 32) * 2;

    float acc[5][4];
    #pragma unroll
    for (int ni = 0; ni < 5; ni++)
        #pragma unroll
        for (int r = 0; r < 4; r++) acc[ni][r] = 0.f;

    int r0i = tid >> 3,           c0i = (tid & 7) * 8;
    int r1i = (tid + 256) >> 3,   c1i = c0i;
    int n0 = blockIdx.y * 512;

    auto load_chunk = [&](int s, int buf){
        int nb = n0 + s * 64;
        uint32_t ksb = ksb0 + buf * KSTG;
        uint32_t vsb = vsb0 + buf * VSTG;
        cpa16(ksb + (uint32_t)(r0i*KVAPK + c0i)*2, kbase + (size_t)(nb + r0i)*1536 + c0i);
        cpa16(ksb + (uint32_t)(r1i*KVAPK + c1i)*2, kbase + (size_t)(nb + r1i)*1536 + c1i);
        cpa16(vsb + (uint32_t)(r0i*KVAPV + c0i)*2, vbase + (size_t)(nb + r0i)*1536 + c0i);
        cpa16(vsb + (uint32_t)(r1i*KVAPV + c1i)*2, vbase + (size_t)(nb + r1i)*1536 + c1i);
    };

    __syncthreads();           // vext init visible before first compute
    load_chunk(0, 0); cpa_commit();

    for (int s = 0; s < 8; s++){
        if (s + 1 < 8) load_chunk(s + 1, (s + 1) & 1);
        cpa_commit();
        cpa_wait<1>();
        __syncthreads();
        uint32_t ksb = ksb0 + (s & 1) * KSTG;
        uint32_t vsb = vsb0 + (s & 1) * VSTG;
        #pragma unroll
        for (int kk = 0; kk < 4; kk++){
            uint32_t a[4], bf[5][2];
            ldsm4t(a[0], a[1], a[2], a[3],
                   ksb + aoff + (uint32_t)(kk * 16 * KVAPK) * 2);
            #pragma unroll
            for (int p = 0; p < 2; p++)
                ldsm4t(bf[2*p][0], bf[2*p][1], bf[2*p+1][0], bf[2*p+1][1],
                       vsb + boff + (uint32_t)(p * 16 + kk * 16 * KVAPV) * 2);
            ldsm2t(bf[4][0], bf[4][1],
                   vsb + b2off + (uint32_t)(kk * 16 * KVAPV) * 2);
            #pragma unroll
            for (int ni = 0; ni < 5; ni++)
                mma_f16(acc[ni], a, bf[ni]);
        }
        __syncthreads();
    }

    float* kvout = g_kv + bh * 4096;
    #pragma unroll
    for (int ni = 0; ni < 5; ni++){
        #pragma unroll
        for (int rr = 0; rr < 2; rr++){
            int r = warpM + rr * 8 + gid;
            int c = warpN + ni * 8 + tig * 2;
            if (c < 64){
                atomicAdd(&kvout[r * 64 + c],     acc[ni][rr*2+0]);
                atomicAdd(&kvout[r * 64 + c + 1], acc[ni][rr*2+1]);
            } else if (c == 64){
                atomicAdd(&g_ksum[bh * 64 + r], acc[ni][rr*2+0]);
            }
        }
    }
}

// ---------------- kvfin: build fp16 B matrix [80][64] per bh -----------------
__global__ void kvfin_kernel()
{
    int bh = blockIdx.x;
    int tid = threadIdx.x;
    for (int i = tid; i < 80*64; i += 256){
        int n = i >> 6, d = i & 63;
        float v;
        if (n < 64)      v = g_kv[bh * 4096 + d * 64 + n];
        else if (n == 64) v = fmaxf(g_ksum[bh * 64 + d], CLAMPF);
        else             v = 0.f;
        g_kvbh[bh * 5120 + i] = __float2half(v);
    }
}

// ---------------- attn via mma: D = q @ [kv | norms]^T, divide, -> fp16 ------
#define APAD 72
__global__ __launch_bounds__(256)
void attn_kernel(const __half* __restrict__ qkv, __half* __restrict__ attn)
{
    __shared__ __half qs[128][APAD];
    __shared__ __half bs[80][APAD];
    int bh = blockIdx.x;
    int b = bh >> 3, h = bh & 7;
    int tok0 = blockIdx.y * 128;
    int tid = threadIdx.x;
    int wid = tid >> 5, lane = tid & 31;
    int gid = lane >> 2, tig = lane & 3;
    const __half* qbase = qkv + (size_t)(b*NN + tok0) * 1536 + h*64;
    const __half* kvb = g_kvbh + bh * 5120;

    uint32_t qsb = smem_u32(&qs[0][0]);
    uint32_t bsb = smem_u32(&bs[0][0]);
    #pragma unroll
    for (int i = 0; i < 4; i++){
        int idx = tid + i * 256;
        int row = idx >> 3, c = (idx & 7) * 8;
        cpa16(qsb + (uint32_t)(row * APAD + c) * 2, qbase + (size_t)row * 1536 + c);
    }
    #pragma unroll
    for (int i = 0; i < 3; i++){
        int idx = tid + i * 256;
        if (idx < 640){
            int row = idx >> 3, c = (idx & 7) * 8;
            cpa16(bsb + (uint32_t)(row * APAD + c) * 2, kvb + row * 64 + c);
        }
    }
    cpa_commit();
    cpa_wait<0>();
    __syncthreads();

    int aRow = wid * 16 + (lane & 15);
    int aCol = (lane >> 4) * 8;
    int bRow = (lane >> 4) * 8 + (lane & 7);
    int bCol = ((lane >> 3) & 1) * 8;
    uint32_t aBase = qsb + (uint32_t)(aRow * APAD + aCol) * 2;
    uint32_t bBase = bsb + (uint32_t)(bRow * APAD + bCol) * 2;

    float acc[10][4];
    #pragma unroll
    for (int ni = 0; ni < 10; ni++)
        #pragma unroll
        for (int r = 0; r < 4; r++) acc[ni][r] = 0.f;

    #pragma unroll
    for (int ks = 0; ks < 4; ks++){
        int k0 = ks * 16;
        uint32_t a[4], bf[10][2];
        ldsm4(a[0], a[1], a[2], a[3], aBase + (uint32_t)(k0 * 2));
        #pragma unroll
        for (int p = 0; p < 5; p++){
            uint32_t bd = bBase + (uint32_t)(p * 16 * APAD + k0) * 2;
            ldsm4(bf[2*p][0], bf[2*p][1], bf[2*p+1][0], bf[2*p+1][1], bd);
        }
        #pragma unroll
        for (int ni = 0; ni < 9; ni++)
            mma_f16(acc[ni], a, bf[ni]);
    }

    float d0 = __shfl_sync(0xffffffffu, acc[8][0], lane & 0x1C);
    float d8 = __shfl_sync(0xffffffffu, acc[8][2], lane & 0x1C);
    float i0 = 1.0f / fmaxf(d0, CLAMPF);
    float i8 = 1.0f / fmaxf(d8, CLAMPF);

    __half* obase = attn + (size_t)(b*NN + tok0 + wid*16) * CC + h*64;
    #pragma unroll
    for (int ni = 0; ni < 8; ni++){
        int c = ni * 8 + tig * 2;
        __half2 o0{__float2half(acc[ni][0] * i0), __float2half(acc[ni][1] * i0)};
        __half2 o8{__float2half(acc[ni][2] * i8), __float2half(acc[ni][3] * i8)};
        *(__half2*)(obase + (size_t)gid * CC + c) = o0;
        *(__half2*)(obase + (size_t)(gid + 8) * CC + c) = o8;
    }
}

// ---------------- conv1: fused LN2-apply + dw7x7 + gelu + bn stats -----------
// 16x8 spatial tile x 32 channels; 256 thr = 32 ch x 8 ow, 16 oh each.
__global__ __launch_bounds__(256)
void conv1_kernel(const __half* __restrict__ ap, const float* __restrict__ cw,
                  const float* __restrict__ cb, const float* __restrict__ lg,
                  const float* __restrict__ lb)
{
    int b  = blockIdx.z;
    int c0 = blockIdx.y * 32;
    int h0 = (blockIdx.x >> 3) * 16;
    int w0 = (blockIdx.x & 7) * 8;
    __shared__ float ins[22][14][32];
    __shared__ float ws[32][49];
    __shared__ float sg[32], sb[32];
    __shared__ float rsum[8][32], rsq[8][32];
    int tid = threadIdx.x;
    if (tid < 32){ sg[tid] = lg[c0 + tid]; sb[tid] = lb[c0 + tid]; }
    for (int i = tid; i < 32 * 49; i += 256)
        ws[i / 49][i % 49] = cw[(c0 + i / 49) * 49 + (i % 49)];
    __syncthreads();
    for (int i = tid; i < 22 * 14 * 16; i += 256) {
        int ic = (i & 15) * 2; int pos = i >> 4;
        int iw = pos % 14, ih = pos / 14;
        int gh = h0 + ih - 3, gw = w0 + iw - 3;
        float vx = 0.f, vy = 0.f;
        if (gh >= 0 && gh < HH && gw >= 0 && gw < WW){
            size_t tok = (size_t)(b*NN) + gh*WW + gw;
            __half2 a2 = *(const __half2*)(ap + tok * CC + c0 + ic);
            float2 af = __half22float2(a2);
            float mu = g_mu[tok], ri = g_rinv[tok];
            vx = (af.x - mu) * ri * sg[ic]     + sb[ic];
            vy = (af.y - mu) * ri * sg[ic + 1] + sb[ic + 1];
        }
        ins[ih][iw][ic]     = vx;
        ins[ih][iw][ic + 1] = vy;
    }
    __syncthreads();
    int oc = tid & 31;
    int ow = tid >> 5;
    float wr[49];
    #pragma unroll
    for (int j = 0; j < 49; j++) wr[j] = ws[oc][j];
    float bias = cb[c0 + oc];
    float acc[16];
    #pragma unroll
    for (int oh = 0; oh < 16; oh++) acc[oh] = bias;
    #pragma unroll
    for (int ih = 0; ih < 22; ih++){
        float v[7];
        #pragma unroll
        for (int dw = 0; dw < 7; dw++) v[dw] = ins[ih][ow + dw][oc];
        #pragma unroll
        for (int oh = 0; oh < 16; oh++){
            int dh = ih - oh;
            if (dh >= 0 && dh < 7){
                #pragma unroll
                for (int dw = 0; dw < 7; dw++)
                    acc[oh] += v[dw] * wr[dh * 7 + dw];
            }
        }
    }
    float psum = 0.f, psq = 0.f;
    #pragma unroll
    for (int oh = 0; oh < 16; oh++){
        float yv = acc[oh] * normcdff(acc[oh]);
        g_y[((size_t)(b*NN) + (h0+oh)*WW + (w0+ow)) * CC + c0 + oc] = __float2half(yv);
        psum += yv; psq += yv * yv;
    }
    rsum[ow][oc] = psum; rsq[ow][oc] = psq;
    __syncthreads();
    if (tid < 32) {
        float s = 0.f, q = 0.f;
        #pragma unroll
        for (int i = 0; i < 8; i++) { s += rsum[i][tid]; q += rsq[i][tid]; }
        atomicAdd(&g_sum[c0 + tid], s);
        atomicAdd(&g_sumsq[c0 + tid], q);
    }
}

// ---------------- conv2: BN-apply + depthwise 7x7 + triple residual ----------
__global__ __launch_bounds__(256)
void conv2_kernel(const float* __restrict__ x, const float* __restrict__ cw,
                  const float* __restrict__ cb, const float* __restrict__ bng,
                  const float* __restrict__ bnb, float* __restrict__ out)
{
    int b  = blockIdx.z;
    int c0 = blockIdx.y * 32;
    int h0 = (blockIdx.x >> 3) * 16;
    int w0 = (blockIdx.x & 7) * 8;
    __shared__ float ins[22][14][32];
    __shared__ float ws[32][49];
    __shared__ float scs[32], shs[32];
    int tid = threadIdx.x;
    if (tid < 32) {
        int c = c0 + tid;
        float m   = g_sum[c]   * (1.0f / (float)NTOK);
        float var = g_sumsq[c] * (1.0f / (float)NTOK) - m * m;
        float inv = rsqrtf(var + EPSF);
        float sc = bng[c] * inv;
        scs[tid] = sc;
        shs[tid] = bnb[c] - m * sc;
    }
    for (int i = tid; i < 32 * 49; i += 256)
        ws[i / 49][i % 49] = cw[(c0 + i / 49) * 49 + (i % 49)];
    __syncthreads();
    for (int i = tid; i < 22 * 14 * 16; i += 256) {
        int ic = (i & 15) * 2; int pos = i >> 4;
        int iw = pos % 14, ih = pos / 14;
        int gh = h0 + ih - 3, gw = w0 + iw - 3;
        float vx = 0.f, vy = 0.f;
        if (gh >= 0 && gh < HH && gw >= 0 && gw < WW){
            __half2 y2 = *(const __half2*)(&g_y[((size_t)(b*NN) + gh*WW + gw) * CC + c0 + ic]);
            float2 yf = __half22float2(y2);
            vx = yf.x * scs[ic]     + shs[ic];
            vy = yf.y * scs[ic + 1] + shs[ic + 1];
        }
        ins[ih][iw][ic]     = vx;
        ins[ih][iw][ic + 1] = vy;
    }
    __syncthreads();
    int oc = tid & 31;
    int ow = tid >> 5;
    float wr[49];
    #pragma unroll
    for (int j = 0; j < 49; j++) wr[j] = ws[oc][j];
    float bias = cb[c0 + oc];
    float acc[16];
    #pragma unroll
    for (int oh = 0; oh < 16; oh++) acc[oh] = bias;
    #pragma unroll
    for (int ih = 0; ih < 22; ih++){
        float v[7];
        #pragma unroll
        for (int dw = 0; dw < 7; dw++) v[dw] = ins[ih][ow + dw][oc];
        #pragma unroll
        for (int oh = 0; oh < 16; oh++){
            int dh = ih - oh;
            if (dh >= 0 && dh < 7){
                #pragma unroll
                for (int dw = 0; dw < 7; dw++)
                    acc[oh] += v[dw] * wr[dh * 7 + dw];
            }
        }
    }
    #pragma unroll
    for (int oh = 0; oh < 16; oh++){
        size_t idx = ((size_t)(b*NN) + (h0+oh)*WW + (w0+ow)) * CC + c0 + oc;
        out[idx] = x[idx] + __half2float(g_attnproj[idx]) + acc[oh];
    }
}

// ---------------- launch ----------------------------------------------------
extern "C" void kernel_launch(void* const* d_in, const int* in_sizes, int n_in,
                              void* d_out, int out_size)
{
    const float* x      = (const float*)d_in[0];
    const float* qkv_w  = (const float*)d_in[1];
    const float* qkv_b  = (const float*)d_in[2];
    const float* out_w  = (const float*)d_in[3];
    const float* out_b  = (const float*)d_in[4];
    const float* pre_g  = (const float*)d_in[5];
    const float* pre_b  = (const float*)d_in[6];
    const float* lcm_g  = (const float*)d_in[7];
    const float* lcm_b  = (const float*)d_in[8];
    const float* ci_w   = (const float*)d_in[9];
    const float* ci_b   = (const float*)d_in[10];
    const float* bn_g   = (const float*)d_in[11];
    const float* bn_b   = (const float*)d_in[12];
    const float* co_w   = (const float*)d_in[13];
    const float* co_b   = (const float*)d_in[14];
    float* out = (float*)d_out;

    __half *p_normedh, *p_qkvh, *p_attnh, *p_attnproj, *p_wqkvTh, *p_woutTh;
    cudaGetSymbolAddress((void**)&p_normedh,  g_normedh);
    cudaGetSymbolAddress((void**)&p_qkvh,     g_qkvh);
    cudaGetSymbolAddress((void**)&p_attnh,    g_attnh);
    cudaGetSymbolAddress((void**)&p_attnproj, g_attnproj);
    cudaGetSymbolAddress((void**)&p_wqkvTh,   g_wqkvTh);
    cudaGetSymbolAddress((void**)&p_woutTh,   g_woutTh);

    cudaFuncSetAttribute(gemm_mma_kernel<__half, false>,
        cudaFuncAttributeMaxDynamicSharedMemorySize, GSMEM);
    cudaFuncSetAttribute(gemm_mma_kernel<__half, true>,
        cudaFuncAttributeMaxDynamicSharedMemorySize, GSMEM);

    // 1. merged weight transpose ([K,N] -> [N,K], fp16)
    transpose_kernel<<<dim3(64, 16), dim3(32,8)>>>(qkv_w, out_w, p_wqkvTh, p_woutTh);
    // 2. zero accumulators
    zero_kernel<<<(BB*HEADS*HD*HD + 255) / 256, 256>>>();
    // 3. pre-layernorm -> fp16
    ln_kernel<<<NTOK, 128>>>(x, pre_g, pre_b, p_normedh);
    // 4. qkv gemm (3-stage pipeline, cp.async.cg) + relu on cols [0,1024)
    gemm_mma_kernel<__half, false><<<dim3(1536/128, NTOK/128), 256, GSMEM>>>(
        p_normedh, p_wqkvTh, qkv_b, p_qkvh, 1536, 1024);
    // 5. kv outer-product + ksum via mma (2-stage pipeline)
    kv_kernel<<<dim3(BB*HEADS, 8), 256>>>(p_qkvh);
    // 6. build fp16 [kv | norms] B matrices
    kvfin_kernel<<<BB*HEADS, 256>>>();
    // 7. attention apply via mma -> fp16
    attn_kernel<<<dim3(BB*HEADS, 32), 256>>>(p_qkvh, p_attnh);
    // 8. output projection + fused LN2 row sums
    gemm_mma_kernel<__half, true><<<dim3(CC/128, NTOK/128), 256, GSMEM>>>(
        p_attnh, p_woutTh, out_b, p_attnproj, 512, 0);
    // 9. LN2 finalize (sums -> mu, rinv)
    ln_fin_kernel<<<NTOK/256, 256>>>();
    // 10. conv1 (LN2-apply fused, 16x8 tiles) + gelu + bn stats -> fp16 y
    conv1_kernel<<<dim3(32, CC/32, BB), 256>>>(p_attnproj, ci_w, ci_b, lcm_g, lcm_b);
    // 11. bn apply + conv2 (16x8 tiles) + triple residual -> out
    conv2_kernel<<<dim3(32, CC/32, BB), 256>>>(x, co_w, co_b, bn_g, bn_b, out);
}